// round 1
// baseline (speedup 1.0000x reference)
#include <cuda_runtime.h>
#include <cuda_bf16.h>
#include <mma.h>

using namespace nvcuda;

// Problem constants (fixed by the reference: B=8,S=2048,D=1024,E=8,F=4096)
#define T_TOK 16384
#define DIM   1024
#define NE    8
#define FF    4096

// ---------------- scratch (device globals: allocation-free rule) ----------
__device__ int   g_counts[NE];
__device__ int   g_off[NE + 1];
__device__ int   g_cursor[NE];
__device__ int   g_perm[T_TOK];
__device__ int   g_expidx[T_TOK];
__device__ float g_H[(size_t)T_TOK * FF];   // 256 MB fp32 hidden activations

// ---------------- small kernels -------------------------------------------
__global__ void zero_kernel() {
    if (threadIdx.x < NE) g_counts[threadIdx.x] = 0;
}

// One warp per token: logits = x_t @ router_w + router_b, argmax (first max).
__global__ void router_kernel(const float* __restrict__ x,
                              const float* __restrict__ rw,
                              const float* __restrict__ rb) {
    int warp = (blockIdx.x * blockDim.x + threadIdx.x) >> 5;
    int lane = threadIdx.x & 31;
    if (warp >= T_TOK) return;
    const float* xr = x + (size_t)warp * DIM;
    float acc[NE];
#pragma unroll
    for (int e = 0; e < NE; e++) acc[e] = 0.f;
    for (int d = lane; d < DIM; d += 32) {
        float xv = xr[d];
        const float4* w4 = (const float4*)(rw + d * NE);
        float4 a = w4[0], b = w4[1];
        acc[0] += xv * a.x; acc[1] += xv * a.y; acc[2] += xv * a.z; acc[3] += xv * a.w;
        acc[4] += xv * b.x; acc[5] += xv * b.y; acc[6] += xv * b.z; acc[7] += xv * b.w;
    }
#pragma unroll
    for (int o = 16; o > 0; o >>= 1)
#pragma unroll
        for (int e = 0; e < NE; e++) acc[e] += __shfl_down_sync(0xffffffffu, acc[e], o);
    if (lane == 0) {
        int bi = 0;
        float bv = acc[0] + rb[0];
#pragma unroll
        for (int e = 1; e < NE; e++) {
            float v = acc[e] + rb[e];
            if (v > bv) { bv = v; bi = e; }   // strict > keeps first max (jnp.argmax)
        }
        g_expidx[warp] = bi;
        atomicAdd(&g_counts[bi], 1);
    }
}

// Prefix-sum offsets (E=8, trivially single-thread) + load-balance loss.
__global__ void setup_kernel(float* out_loss, int write_loss) {
    int off = 0;
    for (int e = 0; e < NE; e++) { g_off[e] = off; g_cursor[e] = off; off += g_counts[e]; }
    g_off[NE] = off;
    if (write_loss) {
        float lb = 0.f;
        for (int e = 0; e < NE; e++) {
            float u = (float)g_counts[e] / (float)T_TOK - 1.0f / NE;
            lb += u * u;
        }
        *out_loss = lb / NE;
    }
}

__global__ void scatter_kernel() {
    int t = blockIdx.x * blockDim.x + threadIdx.x;
    if (t >= T_TOK) return;
    int e = g_expidx[t];
    int p = atomicAdd(&g_cursor[e], 1);
    g_perm[p] = t;
}

// ---------------- grouped GEMM (tf32 wmma) ---------------------------------
// C[p, n] = act( A[row(p), :K] @ W[e, :K, n] + bias[e, n] )
//   GATHER_A : A row index = g_perm[p]   (GEMM1, A = x)
//   SCATTER_C: C row index = g_perm[p]   (GEMM2, C = out)
//   RELU     : apply ReLU (GEMM1)
// W is [E, K, N] row-major with N contiguous (matches w1 / w2 layout).
constexpr int BM = 128, BN = 64, BK = 32;
constexpr int ALD = BK + 4;   // 36 floats (144B, 16B multiple)
constexpr int BLD = BN + 4;   // 68 floats (272B, 16B multiple)
constexpr int MT_STRIDE = 32; // gridDim.y; blocks loop over m-tiles

template <bool GATHER_A, bool SCATTER_C, bool RELU>
__global__ __launch_bounds__(256)
void moe_gemm(const float* __restrict__ A, const float* __restrict__ W,
              const float* __restrict__ bias, float* __restrict__ C,
              int K, int N) {
    __shared__ __align__(16) float As[BM][ALD];
    __shared__ __align__(16) float Bs[BK][BLD];
    __shared__ __align__(16) float Cs[8][16 * 20];  // per-warp epilogue staging

    const int e    = blockIdx.z;
    const int m0   = g_off[e];
    const int rows = g_off[e + 1] - m0;
    const int n0   = blockIdx.x * BN;
    const float* We = W + (size_t)e * K * N;
    const float* be = bias + (size_t)e * N;

    const int warp = threadIdx.x >> 5;
    const int lane = threadIdx.x & 31;
    const int wm = warp & 3;   // 4 warps over M (32 rows each)
    const int wn = warp >> 2;  // 2 warps over N (32 cols each)
    const int c4 = threadIdx.x & 7;

    for (int tm = blockIdx.y; tm * BM < rows; tm += MT_STRIDE) {
        const int rowt = tm * BM;

        // Precompute the 4 A-row pointers this thread stages each K-step.
        const float* aptr[4];
        bool aval[4];
#pragma unroll
        for (int i = 0; i < 4; i++) {
            int r = (threadIdx.x >> 3) + 32 * i;
            aval[i] = (rowt + r) < rows;
            if (aval[i]) {
                int p = m0 + rowt + r;
                aptr[i] = GATHER_A ? A + (size_t)g_perm[p] * K
                                   : A + (size_t)p * K;
            } else {
                aptr[i] = A;
            }
        }

        wmma::fragment<wmma::accumulator, 16, 16, 8, float> fc[2][2];
#pragma unroll
        for (int i = 0; i < 2; i++)
#pragma unroll
            for (int j = 0; j < 2; j++) wmma::fill_fragment(fc[i][j], 0.f);

        for (int kb = 0; kb < K; kb += BK) {
            // Stage A tile (128x32), gathered rows, float4, zero-fill tail rows.
#pragma unroll
            for (int i = 0; i < 4; i++) {
                int r = (threadIdx.x >> 3) + 32 * i;
                float4 v = make_float4(0.f, 0.f, 0.f, 0.f);
                if (aval[i]) v = *(const float4*)(aptr[i] + kb + c4 * 4);
                *(float4*)&As[r][c4 * 4] = v;
            }
            // Stage B tile (32x64), N contiguous.
#pragma unroll
            for (int i = 0; i < 2; i++) {
                int slot = threadIdx.x + i * 256;
                int kr  = slot >> 4;
                int cc4 = slot & 15;
                float4 v = *(const float4*)(We + (size_t)(kb + kr) * N + n0 + cc4 * 4);
                *(float4*)&Bs[kr][cc4 * 4] = v;
            }
            __syncthreads();

#pragma unroll
            for (int kk = 0; kk < BK / 8; kk++) {
                wmma::fragment<wmma::matrix_a, 16, 16, 8, wmma::precision::tf32,
                               wmma::row_major> fa[2];
                wmma::fragment<wmma::matrix_b, 16, 16, 8, wmma::precision::tf32,
                               wmma::row_major> fb[2];
#pragma unroll
                for (int i = 0; i < 2; i++) {
                    wmma::load_matrix_sync(fa[i], &As[wm * 32 + i * 16][kk * 8], ALD);
#pragma unroll
                    for (int t = 0; t < fa[i].num_elements; t++)
                        fa[i].x[t] = wmma::__float_to_tf32(fa[i].x[t]);
                }
#pragma unroll
                for (int j = 0; j < 2; j++) {
                    wmma::load_matrix_sync(fb[j], &Bs[kk * 8][wn * 32 + j * 16], BLD);
#pragma unroll
                    for (int t = 0; t < fb[j].num_elements; t++)
                        fb[j].x[t] = wmma::__float_to_tf32(fb[j].x[t]);
                }
#pragma unroll
                for (int i = 0; i < 2; i++)
#pragma unroll
                    for (int j = 0; j < 2; j++)
                        wmma::mma_sync(fc[i][j], fa[i], fb[j], fc[i][j]);
            }
            __syncthreads();
        }

        // Epilogue: per-warp stage 16x16 frag -> smem -> bias(+relu) -> global.
#pragma unroll
        for (int i = 0; i < 2; i++)
#pragma unroll
            for (int j = 0; j < 2; j++) {
                wmma::store_matrix_sync(&Cs[warp][0], fc[i][j], 20, wmma::mem_row_major);
                __syncwarp();
#pragma unroll
                for (int t = 0; t < 8; t++) {
                    int idx = lane + t * 32;
                    int rr = idx >> 4, cc = idx & 15;
                    int r = wm * 32 + i * 16 + rr;
                    int c = wn * 32 + j * 16 + cc;
                    if (rowt + r < rows) {
                        float v = Cs[warp][rr * 20 + cc] + be[n0 + c];
                        if (RELU) v = fmaxf(v, 0.f);
                        size_t orow = SCATTER_C ? (size_t)g_perm[m0 + rowt + r]
                                                : (size_t)(m0 + rowt + r);
                        C[orow * (size_t)N + n0 + c] = v;
                    }
                }
                __syncwarp();
            }
    }
}

// ---------------- launch ----------------------------------------------------
extern "C" void kernel_launch(void* const* d_in, const int* in_sizes, int n_in,
                              void* d_out, int out_size) {
    const float* x  = (const float*)d_in[0];
    const float* rw = (const float*)d_in[1];
    const float* rb = (const float*)d_in[2];
    const float* w1 = (const float*)d_in[3];
    const float* b1 = (const float*)d_in[4];
    const float* w2 = (const float*)d_in[5];
    const float* b2 = (const float*)d_in[6];
    float* out = (float*)d_out;

    void* hp = nullptr;
    cudaGetSymbolAddress(&hp, g_H);
    float* H = (float*)hp;

    const long long main_elems = (long long)T_TOK * DIM;
    int write_loss = ((long long)out_size > main_elems) ? 1 : 0;

    zero_kernel<<<1, 32>>>();
    router_kernel<<<T_TOK / 8, 256>>>(x, rw, rb);
    setup_kernel<<<1, 1>>>(out + (size_t)T_TOK * DIM, write_loss);
    scatter_kernel<<<T_TOK / 256, 256>>>();

    // GEMM1: H[p,f] = relu(x[perm[p],:] @ w1[e] + b1[e])
    moe_gemm<true, false, true>
        <<<dim3(FF / BN, MT_STRIDE, NE), 256>>>(x, w1, b1, H, DIM, FF);
    // GEMM2: out[perm[p],n] = H[p,:] @ w2[e] + b2[e]
    moe_gemm<false, true, false>
        <<<dim3(DIM / BN, MT_STRIDE, NE), 256>>>(H, w2, b2, out, FF, DIM);
}

// round 2
// speedup vs baseline: 1.1461x; 1.1461x over previous
#include <cuda_runtime.h>
#include <cuda_bf16.h>
#include <mma.h>
#include <cstdint>

using namespace nvcuda;

// Problem constants (fixed by the reference: B=8,S=2048,D=1024,E=8,F=4096)
#define T_TOK 16384
#define DIM   1024
#define NE    8
#define FF    4096

// ---------------- scratch (device globals: allocation-free rule) ----------
__device__ int   g_counts[NE];
__device__ int   g_off[NE + 1];
__device__ int   g_cursor[NE];
__device__ int   g_perm[T_TOK];
__device__ int   g_expidx[T_TOK];
__device__ float g_H[(size_t)T_TOK * FF];   // 256 MB fp32 hidden activations

// ---------------- small kernels -------------------------------------------
__global__ void zero_kernel() {
    if (threadIdx.x < NE) g_counts[threadIdx.x] = 0;
}

// One warp per token: logits = x_t @ router_w + router_b, argmax (first max).
__global__ void router_kernel(const float* __restrict__ x,
                              const float* __restrict__ rw,
                              const float* __restrict__ rb) {
    int warp = (blockIdx.x * blockDim.x + threadIdx.x) >> 5;
    int lane = threadIdx.x & 31;
    if (warp >= T_TOK) return;
    const float* xr = x + (size_t)warp * DIM;
    float acc[NE];
#pragma unroll
    for (int e = 0; e < NE; e++) acc[e] = 0.f;
    for (int d = lane; d < DIM; d += 32) {
        float xv = xr[d];
        const float4* w4 = (const float4*)(rw + d * NE);
        float4 a = w4[0], b = w4[1];
        acc[0] += xv * a.x; acc[1] += xv * a.y; acc[2] += xv * a.z; acc[3] += xv * a.w;
        acc[4] += xv * b.x; acc[5] += xv * b.y; acc[6] += xv * b.z; acc[7] += xv * b.w;
    }
#pragma unroll
    for (int o = 16; o > 0; o >>= 1)
#pragma unroll
        for (int e = 0; e < NE; e++) acc[e] += __shfl_down_sync(0xffffffffu, acc[e], o);
    if (lane == 0) {
        int bi = 0;
        float bv = acc[0] + rb[0];
#pragma unroll
        for (int e = 1; e < NE; e++) {
            float v = acc[e] + rb[e];
            if (v > bv) { bv = v; bi = e; }   // strict > keeps first max (jnp.argmax)
        }
        g_expidx[warp] = bi;
        atomicAdd(&g_counts[bi], 1);
    }
}

// Prefix-sum offsets (E=8, trivially single-thread) + load-balance loss.
__global__ void setup_kernel(float* out_loss, int write_loss) {
    int off = 0;
    for (int e = 0; e < NE; e++) { g_off[e] = off; g_cursor[e] = off; off += g_counts[e]; }
    g_off[NE] = off;
    if (write_loss) {
        float lb = 0.f;
        for (int e = 0; e < NE; e++) {
            float u = (float)g_counts[e] / (float)T_TOK - 1.0f / NE;
            lb += u * u;
        }
        *out_loss = lb / NE;
    }
}

__global__ void scatter_kernel() {
    int t = blockIdx.x * blockDim.x + threadIdx.x;
    if (t >= T_TOK) return;
    int e = g_expidx[t];
    int p = atomicAdd(&g_cursor[e], 1);
    g_perm[p] = t;
}

// ---------------- cp.async helpers ------------------------------------------
__device__ __forceinline__ void cpasync16(uint32_t dst, const void* src, bool valid) {
    int sz = valid ? 16 : 0;   // src-size 0 => zero-fill the 16B
    asm volatile("cp.async.cg.shared.global [%0], [%1], 16, %2;\n"
                 :: "r"(dst), "l"(src), "r"(sz));
}
__device__ __forceinline__ void cpasync_commit() {
    asm volatile("cp.async.commit_group;\n" ::: "memory");
}
template <int N>
__device__ __forceinline__ void cpasync_wait() {
    asm volatile("cp.async.wait_group %0;\n" :: "n"(N) : "memory");
}

// ---------------- grouped GEMM (tf32 wmma, cp.async double-buffered) --------
// C[p, n] = act( A[row(p), :K] @ W[e, :K, n] + bias[e, n] )
//   GATHER_A : A row index = g_perm[p]   (GEMM1, A = x)
//   SCATTER_C: C row index = g_perm[p]   (GEMM2, C = out)
//   RELU     : apply ReLU (GEMM1)
// W is [E, K, N] row-major with N contiguous (matches w1 / w2 layout).
constexpr int BM = 128, BN = 128, BK = 16;
constexpr int ALD = BK + 4;   // 20 floats  (80B, 16B multiple)
constexpr int BLD = BN + 4;   // 132 floats (528B, 16B multiple)
constexpr int MT_STRIDE = 16; // gridDim.y; blocks loop over m-tiles

template <bool GATHER_A, bool SCATTER_C, bool RELU>
__global__ __launch_bounds__(256, 2)
void moe_gemm(const float* __restrict__ A, const float* __restrict__ W,
              const float* __restrict__ bias, float* __restrict__ C,
              int K, int N) {
    __shared__ __align__(16) float As[2][BM][ALD];   // 20480 B
    __shared__ __align__(16) float Bs[2][BK][BLD];   // 16896 B

    const int e    = blockIdx.z;
    const int m0   = g_off[e];
    const int rows = g_off[e + 1] - m0;
    const int n0   = blockIdx.x * BN;
    const float* We = W + (size_t)e * K * N;
    const float* be = bias + (size_t)e * N;

    const int warp = threadIdx.x >> 5;
    const int lane = threadIdx.x & 31;
    const int wm = warp & 1;   // 2 warps over M (64 rows each)
    const int wn = warp >> 1;  // 4 warps over N (32 cols each)
    const int ktiles = K / BK;

    // smem addresses for cp.async (per-thread fixed slots)
    const int ar_row = threadIdx.x >> 2;          // 0..63, rows r and r+64
    const int ar_c4  = threadIdx.x & 3;           // float4 col within BK=16
    const int b_kr0  = threadIdx.x >> 5;          // slot0 row 0..7
    const int b_c4   = threadIdx.x & 31;          // float4 col within BN=128

    uint32_t sA[2][2], sB[2][2];
#pragma unroll
    for (int s = 0; s < 2; s++) {
        sA[s][0] = (uint32_t)__cvta_generic_to_shared(&As[s][ar_row][ar_c4 * 4]);
        sA[s][1] = (uint32_t)__cvta_generic_to_shared(&As[s][ar_row + 64][ar_c4 * 4]);
        sB[s][0] = (uint32_t)__cvta_generic_to_shared(&Bs[s][b_kr0][b_c4 * 4]);
        sB[s][1] = (uint32_t)__cvta_generic_to_shared(&Bs[s][b_kr0 + 8][b_c4 * 4]);
    }

    for (int tm = blockIdx.y; tm * BM < rows; tm += MT_STRIDE) {
        const int rowt = tm * BM;

        // Per-thread A-row source pointers (2 rows per thread), gathered.
        const float* aptr[2];
        bool aval[2];
#pragma unroll
        for (int i = 0; i < 2; i++) {
            int r = ar_row + 64 * i;
            aval[i] = (rowt + r) < rows;
            int p = m0 + min(rowt + r, rows - 1);
            aptr[i] = GATHER_A ? A + (size_t)g_perm[p] * K
                               : A + (size_t)p * K;
        }

        wmma::fragment<wmma::accumulator, 16, 16, 8, float> fc[4][2];
#pragma unroll
        for (int i = 0; i < 4; i++)
#pragma unroll
            for (int j = 0; j < 2; j++) wmma::fill_fragment(fc[i][j], 0.f);

        // ---- prefetch stage 0 ----
        {
            const int kb = 0;
#pragma unroll
            for (int i = 0; i < 2; i++)
                cpasync16(sA[0][i], aptr[i] + kb + ar_c4 * 4, aval[i]);
#pragma unroll
            for (int i = 0; i < 2; i++)
                cpasync16(sB[0][i], We + (size_t)(kb + b_kr0 + 8 * i) * N + n0 + b_c4 * 4, true);
            cpasync_commit();
        }

        for (int kt = 0; kt < ktiles; kt++) {
            const int cur = kt & 1;
            if (kt + 1 < ktiles) {
                const int nxt = cur ^ 1;
                const int kb = (kt + 1) * BK;
#pragma unroll
                for (int i = 0; i < 2; i++)
                    cpasync16(sA[nxt][i], aptr[i] + kb + ar_c4 * 4, aval[i]);
#pragma unroll
                for (int i = 0; i < 2; i++)
                    cpasync16(sB[nxt][i], We + (size_t)(kb + b_kr0 + 8 * i) * N + n0 + b_c4 * 4, true);
                cpasync_commit();
                cpasync_wait<1>();
            } else {
                cpasync_wait<0>();
            }
            __syncthreads();

#pragma unroll
            for (int kk = 0; kk < BK / 8; kk++) {
                wmma::fragment<wmma::matrix_a, 16, 16, 8, wmma::precision::tf32,
                               wmma::row_major> fa[4];
                wmma::fragment<wmma::matrix_b, 16, 16, 8, wmma::precision::tf32,
                               wmma::row_major> fb[2];
#pragma unroll
                for (int i = 0; i < 4; i++) {
                    wmma::load_matrix_sync(fa[i], &As[cur][wm * 64 + i * 16][kk * 8], ALD);
#pragma unroll
                    for (int t = 0; t < fa[i].num_elements; t++)
                        fa[i].x[t] = wmma::__float_to_tf32(fa[i].x[t]);
                }
#pragma unroll
                for (int j = 0; j < 2; j++) {
                    wmma::load_matrix_sync(fb[j], &Bs[cur][kk * 8][wn * 32 + j * 16], BLD);
#pragma unroll
                    for (int t = 0; t < fb[j].num_elements; t++)
                        fb[j].x[t] = wmma::__float_to_tf32(fb[j].x[t]);
                }
#pragma unroll
                for (int i = 0; i < 4; i++)
#pragma unroll
                    for (int j = 0; j < 2; j++)
                        wmma::mma_sync(fc[i][j], fa[i], fb[j], fc[i][j]);
            }
            __syncthreads();
        }

        // ---- epilogue: stage frags via smem (aliased over As), float4 out ----
        float* stage = &As[0][0][0] + warp * (16 * 20);
#pragma unroll
        for (int i = 0; i < 4; i++)
#pragma unroll
            for (int j = 0; j < 2; j++) {
                wmma::store_matrix_sync(stage, fc[i][j], 20, wmma::mem_row_major);
                __syncwarp();
#pragma unroll
                for (int t = 0; t < 2; t++) {
                    int idx = lane + 32 * t;          // 0..63 -> 16 rows x 4 float4
                    int rr = idx >> 2, cc4 = idx & 3;
                    int r = wm * 64 + i * 16 + rr;
                    int c = n0 + wn * 32 + j * 16 + cc4 * 4;
                    if (rowt + r < rows) {
                        float4 v = *(float4*)&stage[rr * 20 + cc4 * 4];
                        float4 b = *(const float4*)&be[c];
                        v.x += b.x; v.y += b.y; v.z += b.z; v.w += b.w;
                        if (RELU) {
                            v.x = fmaxf(v.x, 0.f); v.y = fmaxf(v.y, 0.f);
                            v.z = fmaxf(v.z, 0.f); v.w = fmaxf(v.w, 0.f);
                        }
                        size_t orow = SCATTER_C ? (size_t)g_perm[m0 + rowt + r]
                                                : (size_t)(m0 + rowt + r);
                        *(float4*)&C[orow * (size_t)N + c] = v;
                    }
                }
                __syncwarp();
            }
        __syncthreads();   // staging aliases As[0]; next tm-iter prefetch writes it
    }
}

// ---------------- launch ----------------------------------------------------
extern "C" void kernel_launch(void* const* d_in, const int* in_sizes, int n_in,
                              void* d_out, int out_size) {
    const float* x  = (const float*)d_in[0];
    const float* rw = (const float*)d_in[1];
    const float* rb = (const float*)d_in[2];
    const float* w1 = (const float*)d_in[3];
    const float* b1 = (const float*)d_in[4];
    const float* w2 = (const float*)d_in[5];
    const float* b2 = (const float*)d_in[6];
    float* out = (float*)d_out;

    void* hp = nullptr;
    cudaGetSymbolAddress(&hp, g_H);
    float* H = (float*)hp;

    const long long main_elems = (long long)T_TOK * DIM;
    int write_loss = ((long long)out_size > main_elems) ? 1 : 0;

    zero_kernel<<<1, 32>>>();
    router_kernel<<<T_TOK / 8, 256>>>(x, rw, rb);
    setup_kernel<<<1, 1>>>(out + (size_t)T_TOK * DIM, write_loss);
    scatter_kernel<<<T_TOK / 256, 256>>>();

    // GEMM1: H[p,f] = relu(x[perm[p],:] @ w1[e] + b1[e])
    moe_gemm<true, false, true>
        <<<dim3(FF / BN, MT_STRIDE, NE), 256>>>(x, w1, b1, H, DIM, FF);
    // GEMM2: out[perm[p],n] = H[p,:] @ w2[e] + b2[e]
    moe_gemm<false, true, false>
        <<<dim3(DIM / BN, MT_STRIDE, NE), 256>>>(H, w2, b2, out, FF, DIM);
}

// round 4
// speedup vs baseline: 1.1855x; 1.0344x over previous
#include <cuda_runtime.h>
#include <mma.h>
#include <cstdint>

using namespace nvcuda;

// Problem constants (fixed: B=8,S=2048,D=1024,E=8,F=4096)
#define T_TOK 16384
#define DIM   1024
#define NE    8
#define FF    4096

// ---------------- scratch (device globals: allocation-free rule) ----------
__device__ int   g_counts[NE];
__device__ int   g_off[NE + 1];
__device__ int   g_cursor[NE];
__device__ int   g_perm[T_TOK];
__device__ int   g_expidx[T_TOK];
__device__ float g_H[(size_t)T_TOK * FF];          // 256 MB hidden (tf32-rounded)
__device__ float g_xr[(size_t)T_TOK * DIM];        // x rounded to tf32
__device__ float g_w1r[(size_t)NE * DIM * FF];     // w1 rounded to tf32
__device__ float g_w2r[(size_t)NE * DIM * FF];     // w2 rounded to tf32

// ---------------- helpers ---------------------------------------------------
__device__ __forceinline__ float rtf32(float f) {
    uint32_t o;
    asm("cvt.rna.tf32.f32 %0, %1;" : "=r"(o) : "f"(f));
    return __uint_as_float(o);
}
__device__ __forceinline__ void cpasync16(uint32_t dst, const void* src) {
    asm volatile("cp.async.cg.shared.global [%0], [%1], 16;\n"
                 :: "r"(dst), "l"(src));
}
__device__ __forceinline__ void cpasync_commit() {
    asm volatile("cp.async.commit_group;\n" ::: "memory");
}
template <int N>
__device__ __forceinline__ void cpasync_wait() {
    asm volatile("cp.async.wait_group %0;\n" :: "n"(N) : "memory");
}
__device__ __forceinline__ uint32_t smem_u32(const void* p) {
    uint32_t a;
    asm("{ .reg .u64 t; cvta.to.shared.u64 t, %1; cvt.u32.u64 %0, t; }"
        : "=r"(a) : "l"(p));
    return a;
}

// ---------------- small kernels -------------------------------------------
__global__ void zero_kernel() {
    if (threadIdx.x < NE) g_counts[threadIdx.x] = 0;
}

__global__ void router_kernel(const float* __restrict__ x,
                              const float* __restrict__ rw,
                              const float* __restrict__ rb) {
    int warp = (blockIdx.x * blockDim.x + threadIdx.x) >> 5;
    int lane = threadIdx.x & 31;
    if (warp >= T_TOK) return;
    const float* xr = x + (size_t)warp * DIM;
    float acc[NE];
#pragma unroll
    for (int e = 0; e < NE; e++) acc[e] = 0.f;
    for (int d = lane; d < DIM; d += 32) {
        float xv = xr[d];
        const float4* w4 = (const float4*)(rw + d * NE);
        float4 a = w4[0], b = w4[1];
        acc[0] += xv * a.x; acc[1] += xv * a.y; acc[2] += xv * a.z; acc[3] += xv * a.w;
        acc[4] += xv * b.x; acc[5] += xv * b.y; acc[6] += xv * b.z; acc[7] += xv * b.w;
    }
#pragma unroll
    for (int o = 16; o > 0; o >>= 1)
#pragma unroll
        for (int e = 0; e < NE; e++) acc[e] += __shfl_down_sync(0xffffffffu, acc[e], o);
    if (lane == 0) {
        int bi = 0;
        float bv = acc[0] + rb[0];
#pragma unroll
        for (int e = 1; e < NE; e++) {
            float v = acc[e] + rb[e];
            if (v > bv) { bv = v; bi = e; }   // strict > == first max (jnp.argmax)
        }
        g_expidx[warp] = bi;
        atomicAdd(&g_counts[bi], 1);
    }
}

__global__ void setup_kernel(float* out_loss, int write_loss) {
    int off = 0;
    for (int e = 0; e < NE; e++) { g_off[e] = off; g_cursor[e] = off; off += g_counts[e]; }
    g_off[NE] = off;
    if (write_loss) {
        float lb = 0.f;
        for (int e = 0; e < NE; e++) {
            float u = (float)g_counts[e] / (float)T_TOK - 1.0f / NE;
            lb += u * u;
        }
        *out_loss = lb / NE;
    }
}

__global__ void scatter_kernel() {
    int t = blockIdx.x * blockDim.x + threadIdx.x;
    if (t >= T_TOK) return;
    int e = g_expidx[t];
    int p = atomicAdd(&g_cursor[e], 1);
    g_perm[p] = t;
}

// elementwise round-to-tf32 copy (float4, grid-stride)
__global__ void round_tf32_kernel(const float4* __restrict__ in,
                                  float4* __restrict__ out, long n4) {
    long i = (long)blockIdx.x * blockDim.x + threadIdx.x;
    long stride = (long)gridDim.x * blockDim.x;
    for (; i < n4; i += stride) {
        float4 v = in[i];
        v.x = rtf32(v.x); v.y = rtf32(v.y); v.z = rtf32(v.z); v.w = rtf32(v.w);
        out[i] = v;
    }
}

// ---------------- grouped GEMM (tf32 wmma, pre-rounded operands) -----------
// C[p,n] = act( A[row(p), :K] @ W[e, :K, n] + bias[e, n] )
// CTA tile 128x256x16, 8 warps (2M x 4N), warp tile 64x64. 3-stage cp.async.
constexpr int BM = 128, BN = 256, BK = 16;
constexpr int ALD = 20;                    // floats per A smem row (80 B)
constexpr int BLD = 260;                   // floats per B smem row (1040 B)
constexpr int A_STAGE = BM * ALD * 4;      // 10240 B
constexpr int B_STAGE = BK * BLD * 4;      // 16640 B
constexpr int NSTAGE = 3;
constexpr int SMEM_BYTES = NSTAGE * (A_STAGE + B_STAGE) + 256;

template <bool GATHER_A, bool SCATTER_C, bool RELU, bool ROUND_OUT>
__global__ __launch_bounds__(256, 1)
void moe_gemm(const float* __restrict__ A, const float* __restrict__ W,
              const float* __restrict__ bias, float* __restrict__ C,
              int K, int N) {
    extern __shared__ __align__(16) char smem[];
    const uint32_t base  = smem_u32(smem);
    const uint32_t bbase = base + NSTAGE * A_STAGE;

    const int tid  = threadIdx.x;
    const int warp = tid >> 5;
    const int lane = tid & 31;
    const int wm = warp & 1;     // 2 warps over M (64 rows)
    const int wn = warp >> 1;    // 4 warps over N (64 cols)

    const int e    = blockIdx.z;
    const int m0   = g_off[e];
    const int rows = g_off[e + 1] - m0;
    const int n0   = blockIdx.x * BN;
    const float* We = W + (size_t)e * K * N;
    const float* be = bias + (size_t)e * N;
    const int ktiles = K / BK;

    // cp.async per-thread slots
    const int a_r = tid >> 2;          // A rows a_r, a_r+64
    const int a_c = tid & 3;           // float4 col in BK=16
    uint32_t adst[NSTAGE][2], bdst[NSTAGE][4];
    size_t   bsrc[4];
#pragma unroll
    for (int s = 0; s < NSTAGE; s++) {
#pragma unroll
        for (int i = 0; i < 2; i++)
            adst[s][i] = base + s * A_STAGE + (a_r + 64 * i) * (ALD * 4) + a_c * 16;
#pragma unroll
        for (int i = 0; i < 4; i++) {
            int slot = tid + 256 * i;
            int kr = slot >> 6, c4 = slot & 63;
            bdst[s][i] = bbase + s * B_STAGE + kr * (BLD * 4) + c4 * 16;
            if (s == 0) bsrc[i] = (size_t)kr * N + n0 + c4 * 4;
        }
    }

    for (int tm = blockIdx.y; tm * BM < rows; tm += gridDim.y) {
        const int rowt = tm * BM;

        const float* aptr[2];
        bool aval[2];
#pragma unroll
        for (int i = 0; i < 2; i++) {
            int r = a_r + 64 * i;
            aval[i] = (rowt + r) < rows;
            int p = m0 + min(rowt + r, rows - 1);
            aptr[i] = GATHER_A ? A + (size_t)g_perm[p] * K
                               : A + (size_t)p * K;
        }

        wmma::fragment<wmma::accumulator, 16, 16, 8, float> fc[4][4];
#pragma unroll
        for (int i = 0; i < 4; i++)
#pragma unroll
            for (int j = 0; j < 4; j++) wmma::fill_fragment(fc[i][j], 0.f);

        // prefetch k-tiles 0,1
#pragma unroll
        for (int pk = 0; pk < 2; pk++) {
#pragma unroll
            for (int i = 0; i < 2; i++)
                cpasync16(adst[pk][i], aptr[i] + pk * BK + a_c * 4);
#pragma unroll
            for (int i = 0; i < 4; i++)
                cpasync16(bdst[pk][i], We + (size_t)(pk * BK) * N + bsrc[i]);
            cpasync_commit();
        }

        for (int kt = 0; kt < ktiles; kt++) {
            if (kt < ktiles - 1) cpasync_wait<1>();
            else                 cpasync_wait<0>();
            __syncthreads();

            // prefetch kt+2 into stage (kt+2)%3 (safe: all warps past kt-1)
            const int nk = kt + 2;
            if (nk < ktiles) {
                const int s = nk - (nk / 3) * 3;
#pragma unroll
                for (int i = 0; i < 2; i++)
                    cpasync16(adst[s][i], aptr[i] + nk * BK + a_c * 4);
#pragma unroll
                for (int i = 0; i < 4; i++)
                    cpasync16(bdst[s][i], We + (size_t)(nk * BK) * N + bsrc[i]);
                cpasync_commit();
            }

            const int cur = kt - (kt / 3) * 3;
            const float* As = (const float*)(smem + cur * A_STAGE);
            const float* Bs = (const float*)(smem + NSTAGE * A_STAGE + cur * B_STAGE);

#pragma unroll
            for (int kk = 0; kk < BK / 8; kk++) {
                wmma::fragment<wmma::matrix_a, 16, 16, 8, wmma::precision::tf32,
                               wmma::row_major> fa[4];
                wmma::fragment<wmma::matrix_b, 16, 16, 8, wmma::precision::tf32,
                               wmma::row_major> fb[4];
#pragma unroll
                for (int i = 0; i < 4; i++)
                    wmma::load_matrix_sync(fa[i],
                        As + (wm * 64 + i * 16) * ALD + kk * 8, ALD);
#pragma unroll
                for (int j = 0; j < 4; j++)
                    wmma::load_matrix_sync(fb[j],
                        Bs + (kk * 8) * BLD + wn * 64 + j * 16, BLD);
#pragma unroll
                for (int i = 0; i < 4; i++)
#pragma unroll
                    for (int j = 0; j < 4; j++)
                        wmma::mma_sync(fc[i][j], fa[i], fb[j], fc[i][j]);
            }
        }

        __syncthreads();   // everyone done with smem stages; reuse for staging

        // epilogue: per-warp 16x16 staging, bias(+relu)(+round), float4 stores
        float* stage = (float*)(smem) + warp * (16 * ALD);
#pragma unroll
        for (int i = 0; i < 4; i++)
#pragma unroll
            for (int j = 0; j < 4; j++) {
                wmma::store_matrix_sync(stage, fc[i][j], ALD, wmma::mem_row_major);
                __syncwarp();
#pragma unroll
                for (int t = 0; t < 2; t++) {
                    int idx = lane + 32 * t;        // 64 slots: 16 rows x 4 f4
                    int rr = idx >> 2, cc4 = idx & 3;
                    int r = wm * 64 + i * 16 + rr;
                    int c = n0 + wn * 64 + j * 16 + cc4 * 4;
                    if (rowt + r < rows) {
                        float4 v = *(float4*)&stage[rr * ALD + cc4 * 4];
                        float4 b = *(const float4*)&be[c];
                        v.x += b.x; v.y += b.y; v.z += b.z; v.w += b.w;
                        if (RELU) {
                            v.x = fmaxf(v.x, 0.f); v.y = fmaxf(v.y, 0.f);
                            v.z = fmaxf(v.z, 0.f); v.w = fmaxf(v.w, 0.f);
                        }
                        if (ROUND_OUT) {
                            v.x = rtf32(v.x); v.y = rtf32(v.y);
                            v.z = rtf32(v.z); v.w = rtf32(v.w);
                        }
                        size_t orow = SCATTER_C ? (size_t)g_perm[m0 + rowt + r]
                                                : (size_t)(m0 + rowt + r);
                        *(float4*)&C[orow * (size_t)N + c] = v;
                    }
                }
                __syncwarp();
            }
        __syncthreads();   // staging aliases stage 0; next tm prefetch writes it
    }
}

// ---------------- launch ----------------------------------------------------
extern "C" void kernel_launch(void* const* d_in, const int* in_sizes, int n_in,
                              void* d_out, int out_size) {
    const float* x  = (const float*)d_in[0];
    const float* rw = (const float*)d_in[1];
    const float* rb = (const float*)d_in[2];
    const float* w1 = (const float*)d_in[3];
    const float* b1 = (const float*)d_in[4];
    const float* w2 = (const float*)d_in[5];
    const float* b2 = (const float*)d_in[6];
    float* out = (float*)d_out;

    void* p;
    cudaGetSymbolAddress(&p, g_H);   float* H   = (float*)p;
    cudaGetSymbolAddress(&p, g_xr);  float* xr  = (float*)p;
    cudaGetSymbolAddress(&p, g_w1r); float* w1r = (float*)p;
    cudaGetSymbolAddress(&p, g_w2r); float* w2r = (float*)p;

    cudaFuncSetAttribute(moe_gemm<true,  false, true,  true>,
                         cudaFuncAttributeMaxDynamicSharedMemorySize, SMEM_BYTES);
    cudaFuncSetAttribute(moe_gemm<false, true,  false, false>,
                         cudaFuncAttributeMaxDynamicSharedMemorySize, SMEM_BYTES);

    const long long main_elems = (long long)T_TOK * DIM;
    int write_loss = ((long long)out_size > main_elems) ? 1 : 0;

    zero_kernel<<<1, 32>>>();
    router_kernel<<<T_TOK / 8, 256>>>(x, rw, rb);
    setup_kernel<<<1, 1>>>(out + (size_t)T_TOK * DIM, write_loss);
    scatter_kernel<<<T_TOK / 256, 256>>>();

    // pre-round operands to tf32 (RN) once
    round_tf32_kernel<<<1024, 256>>>((const float4*)x,  (float4*)xr,
                                     (long)T_TOK * DIM / 4);
    round_tf32_kernel<<<2048, 256>>>((const float4*)w1, (float4*)w1r,
                                     (long)NE * DIM * FF / 4);
    round_tf32_kernel<<<2048, 256>>>((const float4*)w2, (float4*)w2r,
                                     (long)NE * DIM * FF / 4);

    // GEMM1: H[p,f] = round_tf32(relu(x[perm[p],:] @ w1[e] + b1[e]))
    moe_gemm<true, false, true, true>
        <<<dim3(FF / BN, 16, NE), 256, SMEM_BYTES>>>(xr, w1r, b1, H, DIM, FF);
    // GEMM2: out[perm[p],n] = H[p,:] @ w2[e] + b2[e]
    moe_gemm<false, true, false, false>
        <<<dim3(DIM / BN, 16, NE), 256, SMEM_BYTES>>>(H, w2r, b2, out, FF, DIM);
}

// round 5
// speedup vs baseline: 1.3324x; 1.1239x over previous
#include <cuda_runtime.h>
#include <cuda_bf16.h>
#include <mma.h>
#include <cstdint>

using namespace nvcuda;

// Problem constants (fixed: B=8,S=2048,D=1024,E=8,F=4096)
#define T_TOK 16384
#define DIM   1024
#define NE    8
#define FF    4096

typedef __nv_bfloat16 bf16;

// ---------------- scratch (device globals: allocation-free rule) ----------
__device__ int  g_counts[NE];
__device__ int  g_off[NE + 1];
__device__ int  g_cursor[NE];
__device__ int  g_perm[T_TOK];
__device__ int  g_expidx[T_TOK];
__device__ bf16 g_xh[(size_t)T_TOK * DIM];
__device__ bf16 g_xl[(size_t)T_TOK * DIM];
__device__ bf16 g_w1h[(size_t)NE * DIM * FF];
__device__ bf16 g_w1l[(size_t)NE * DIM * FF];
__device__ bf16 g_w2h[(size_t)NE * DIM * FF];
__device__ bf16 g_w2l[(size_t)NE * DIM * FF];
__device__ bf16 g_Hh[(size_t)T_TOK * FF];
__device__ bf16 g_Hl[(size_t)T_TOK * FF];

// ---------------- helpers ---------------------------------------------------
__device__ __forceinline__ void cpasync16(uint32_t dst, const void* src) {
    asm volatile("cp.async.cg.shared.global [%0], [%1], 16;\n"
                 :: "r"(dst), "l"(src));
}
__device__ __forceinline__ void cpasync_commit() {
    asm volatile("cp.async.commit_group;\n" ::: "memory");
}
template <int N>
__device__ __forceinline__ void cpasync_wait() {
    asm volatile("cp.async.wait_group %0;\n" :: "n"(N) : "memory");
}
__device__ __forceinline__ uint32_t smem_u32(const void* p) {
    uint32_t a;
    asm("{ .reg .u64 t; cvta.to.shared.u64 t, %1; cvt.u32.u64 %0, t; }"
        : "=r"(a) : "l"(p));
    return a;
}

// ---------------- small kernels -------------------------------------------
__global__ void zero_kernel() {
    if (threadIdx.x < NE) g_counts[threadIdx.x] = 0;
}

__global__ void router_kernel(const float* __restrict__ x,
                              const float* __restrict__ rw,
                              const float* __restrict__ rb) {
    int warp = (blockIdx.x * blockDim.x + threadIdx.x) >> 5;
    int lane = threadIdx.x & 31;
    if (warp >= T_TOK) return;
    const float* xr = x + (size_t)warp * DIM;
    float acc[NE];
#pragma unroll
    for (int e = 0; e < NE; e++) acc[e] = 0.f;
    for (int d = lane; d < DIM; d += 32) {
        float xv = xr[d];
        const float4* w4 = (const float4*)(rw + d * NE);
        float4 a = w4[0], b = w4[1];
        acc[0] += xv * a.x; acc[1] += xv * a.y; acc[2] += xv * a.z; acc[3] += xv * a.w;
        acc[4] += xv * b.x; acc[5] += xv * b.y; acc[6] += xv * b.z; acc[7] += xv * b.w;
    }
#pragma unroll
    for (int o = 16; o > 0; o >>= 1)
#pragma unroll
        for (int e = 0; e < NE; e++) acc[e] += __shfl_down_sync(0xffffffffu, acc[e], o);
    if (lane == 0) {
        int bi = 0;
        float bv = acc[0] + rb[0];
#pragma unroll
        for (int e = 1; e < NE; e++) {
            float v = acc[e] + rb[e];
            if (v > bv) { bv = v; bi = e; }   // strict > == first max (jnp.argmax)
        }
        g_expidx[warp] = bi;
        atomicAdd(&g_counts[bi], 1);
    }
}

__global__ void setup_kernel(float* out_loss, int write_loss) {
    int off = 0;
    for (int e = 0; e < NE; e++) { g_off[e] = off; g_cursor[e] = off; off += g_counts[e]; }
    g_off[NE] = off;
    if (write_loss) {
        float lb = 0.f;
        for (int e = 0; e < NE; e++) {
            float u = (float)g_counts[e] / (float)T_TOK - 1.0f / NE;
            lb += u * u;
        }
        *out_loss = lb / NE;
    }
}

__global__ void scatter_kernel() {
    int t = blockIdx.x * blockDim.x + threadIdx.x;
    if (t >= T_TOK) return;
    int e = g_expidx[t];
    int p = atomicAdd(&g_cursor[e], 1);
    g_perm[p] = t;
}

// fp32 -> (hi, lo) bf16 split, 4 elems/thread-iter
__global__ void split_kernel(const float4* __restrict__ in,
                             uint2* __restrict__ hi, uint2* __restrict__ lo,
                             long n4) {
    long i = (long)blockIdx.x * blockDim.x + threadIdx.x;
    long stride = (long)gridDim.x * blockDim.x;
    for (; i < n4; i += stride) {
        float4 v = in[i];
        bf16 h0 = __float2bfloat16(v.x), h1 = __float2bfloat16(v.y);
        bf16 h2 = __float2bfloat16(v.z), h3 = __float2bfloat16(v.w);
        bf16 l0 = __float2bfloat16(v.x - __bfloat162float(h0));
        bf16 l1 = __float2bfloat16(v.y - __bfloat162float(h1));
        bf16 l2 = __float2bfloat16(v.z - __bfloat162float(h2));
        bf16 l3 = __float2bfloat16(v.w - __bfloat162float(h3));
        uint2 hw, lw;
        hw.x = (uint32_t)__bfloat16_as_ushort(h0) |
               ((uint32_t)__bfloat16_as_ushort(h1) << 16);
        hw.y = (uint32_t)__bfloat16_as_ushort(h2) |
               ((uint32_t)__bfloat16_as_ushort(h3) << 16);
        lw.x = (uint32_t)__bfloat16_as_ushort(l0) |
               ((uint32_t)__bfloat16_as_ushort(l1) << 16);
        lw.y = (uint32_t)__bfloat16_as_ushort(l2) |
               ((uint32_t)__bfloat16_as_ushort(l3) << 16);
        hi[i] = hw;
        lo[i] = lw;
    }
}

// ---------------- grouped GEMM: bf16x3 compensated (real HMMA) --------------
// C = act( (Ah+Al) @ (Wh+Wl) + bias )  ~=  Ah@Wh + Ah@Wl + Al@Wh  (fp32 accum)
// CTA tile 128x128x32, 8 warps (2M x 4N), warp tile 64x32. 3-stage cp.async.
constexpr int BM = 128, BN = 128, BK = 32;
constexpr int ALD = 40;                    // bf16 elems per A smem row (80 B)
constexpr int BLD = 136;                   // bf16 elems per B smem row (272 B)
constexpr int A_T = BM * ALD * 2;          // 10240 B per A tile (h or l)
constexpr int B_T = BK * BLD * 2;          // 8704 B per B tile (h or l)
constexpr int STAGE = 2 * A_T + 2 * B_T;   // 37888 B
constexpr int NSTAGE = 3;
constexpr int SMEM_BYTES = NSTAGE * STAGE + 256;

typedef wmma::fragment<wmma::matrix_a, 16, 16, 16, bf16, wmma::row_major> FragA;
typedef wmma::fragment<wmma::matrix_b, 16, 16, 16, bf16, wmma::row_major> FragB;
typedef wmma::fragment<wmma::accumulator, 16, 16, 16, float> FragC;

template <bool GATHER_A, bool SCATTER_C, bool RELU, bool SPLIT_OUT>
__global__ __launch_bounds__(256, 1)
void moe_gemm_b3(const bf16* __restrict__ Ah, const bf16* __restrict__ Al,
                 const bf16* __restrict__ Wh, const bf16* __restrict__ Wl,
                 const float* __restrict__ bias, float* __restrict__ C,
                 bf16* __restrict__ Ch, bf16* __restrict__ Cl,
                 int K, int N) {
    extern __shared__ __align__(16) char smem[];
    const uint32_t base = smem_u32(smem);

    const int tid  = threadIdx.x;
    const int warp = tid >> 5;
    const int lane = tid & 31;
    const int wm = warp & 1;     // 2 warps over M (64 rows)
    const int wn = warp >> 1;    // 4 warps over N (32 cols)

    const int e    = blockIdx.z;
    const int m0   = g_off[e];
    const int rows = g_off[e + 1] - m0;
    const int n0   = blockIdx.x * BN;
    const bf16* Whe = Wh + (size_t)e * K * N;
    const bf16* Wle = Wl + (size_t)e * K * N;
    const float* be = bias + (size_t)e * N;
    const int ktiles = K / BK;

    // cp.async per-thread slots
    const int a_r = tid >> 2;          // A rows a_r, a_r+64
    const int a_c = tid & 3;           // 16B chunk (8 bf16) in BK=32
    const int b_r = tid >> 4;          // B rows b_r, b_r+16
    const int b_c = tid & 15;          // 16B chunk in BN=128

    for (int tm = blockIdx.y; tm * BM < rows; tm += gridDim.y) {
        const int rowt = tm * BM;

        const bf16 *aph[2], *apl[2];
#pragma unroll
        for (int q = 0; q < 2; q++) {
            int r = a_r + 64 * q;
            int p = m0 + min(rowt + r, rows - 1);
            size_t src = GATHER_A ? (size_t)g_perm[p] * K : (size_t)p * K;
            aph[q] = Ah + src;
            apl[q] = Al + src;
        }

        FragC fc[4][2];
#pragma unroll
        for (int i = 0; i < 4; i++)
#pragma unroll
            for (int j = 0; j < 2; j++) wmma::fill_fragment(fc[i][j], 0.f);

        // prefetch k-tiles 0,1
#pragma unroll
        for (int pk = 0; pk < 2; pk++) {
            uint32_t sb = base + pk * STAGE;
            int kb = pk * BK;
#pragma unroll
            for (int q = 0; q < 2; q++) {
                uint32_t aoff = (uint32_t)(a_r + 64 * q) * 80u + a_c * 16u;
                cpasync16(sb + aoff,        aph[q] + kb + a_c * 8);
                cpasync16(sb + A_T + aoff,  apl[q] + kb + a_c * 8);
            }
#pragma unroll
            for (int q = 0; q < 2; q++) {
                uint32_t boff = (uint32_t)(b_r + 16 * q) * 272u + b_c * 16u;
                size_t src = (size_t)(kb + b_r + 16 * q) * N + n0 + b_c * 8;
                cpasync16(sb + 2 * A_T + boff,       Whe + src);
                cpasync16(sb + 2 * A_T + B_T + boff, Wle + src);
            }
            cpasync_commit();
        }

        for (int kt = 0; kt < ktiles; kt++) {
            if (kt < ktiles - 1) cpasync_wait<1>();
            else                 cpasync_wait<0>();
            __syncthreads();

            // prefetch kt+2 into stage (kt+2)%3
            const int nk = kt + 2;
            if (nk < ktiles) {
                const int s = nk - (nk / 3) * 3;
                uint32_t sb = base + s * STAGE;
                int kb = nk * BK;
#pragma unroll
                for (int q = 0; q < 2; q++) {
                    uint32_t aoff = (uint32_t)(a_r + 64 * q) * 80u + a_c * 16u;
                    cpasync16(sb + aoff,        aph[q] + kb + a_c * 8);
                    cpasync16(sb + A_T + aoff,  apl[q] + kb + a_c * 8);
                }
#pragma unroll
                for (int q = 0; q < 2; q++) {
                    uint32_t boff = (uint32_t)(b_r + 16 * q) * 272u + b_c * 16u;
                    size_t src = (size_t)(kb + b_r + 16 * q) * N + n0 + b_c * 8;
                    cpasync16(sb + 2 * A_T + boff,       Whe + src);
                    cpasync16(sb + 2 * A_T + B_T + boff, Wle + src);
                }
                cpasync_commit();
            }

            const int cur = kt - (kt / 3) * 3;
            const bf16* Ahs = (const bf16*)(smem + cur * STAGE);
            const bf16* Als = (const bf16*)(smem + cur * STAGE + A_T);
            const bf16* Bhs = (const bf16*)(smem + cur * STAGE + 2 * A_T);
            const bf16* Bls = (const bf16*)(smem + cur * STAGE + 2 * A_T + B_T);

#pragma unroll
            for (int kk = 0; kk < BK / 16; kk++) {
                FragA fah[4], fal[4];
                FragB fbh[2], fbl[2];
#pragma unroll
                for (int i = 0; i < 4; i++) {
                    const int r = wm * 64 + i * 16;
                    wmma::load_matrix_sync(fah[i], Ahs + r * ALD + kk * 16, ALD);
                    wmma::load_matrix_sync(fal[i], Als + r * ALD + kk * 16, ALD);
                }
#pragma unroll
                for (int j = 0; j < 2; j++) {
                    const int c = wn * 32 + j * 16;
                    wmma::load_matrix_sync(fbh[j], Bhs + kk * 16 * BLD + c, BLD);
                    wmma::load_matrix_sync(fbl[j], Bls + kk * 16 * BLD + c, BLD);
                }
#pragma unroll
                for (int i = 0; i < 4; i++)
#pragma unroll
                    for (int j = 0; j < 2; j++) {
                        wmma::mma_sync(fc[i][j], fah[i], fbh[j], fc[i][j]);
                        wmma::mma_sync(fc[i][j], fah[i], fbl[j], fc[i][j]);
                        wmma::mma_sync(fc[i][j], fal[i], fbh[j], fc[i][j]);
                    }
            }
        }

        __syncthreads();   // done with pipeline smem; reuse for staging

        // epilogue: per-warp 16x16 staging (fp32), bias(+relu), store
        float* stage = (float*)(smem) + warp * (16 * 20);
#pragma unroll
        for (int i = 0; i < 4; i++)
#pragma unroll
            for (int j = 0; j < 2; j++) {
                wmma::store_matrix_sync(stage, fc[i][j], 20, wmma::mem_row_major);
                __syncwarp();
#pragma unroll
                for (int t = 0; t < 2; t++) {
                    int idx = lane + 32 * t;        // 64 slots: 16 rows x 4 f4
                    int rr = idx >> 2, cc4 = idx & 3;
                    int r = wm * 64 + i * 16 + rr;
                    int c = n0 + wn * 32 + j * 16 + cc4 * 4;
                    if (rowt + r < rows) {
                        float4 v = *(float4*)&stage[rr * 20 + cc4 * 4];
                        float4 b = *(const float4*)&be[c];
                        v.x += b.x; v.y += b.y; v.z += b.z; v.w += b.w;
                        if (RELU) {
                            v.x = fmaxf(v.x, 0.f); v.y = fmaxf(v.y, 0.f);
                            v.z = fmaxf(v.z, 0.f); v.w = fmaxf(v.w, 0.f);
                        }
                        if (SPLIT_OUT) {
                            size_t orow = (size_t)(m0 + rowt + r);
                            bf16 h0 = __float2bfloat16(v.x), h1 = __float2bfloat16(v.y);
                            bf16 h2 = __float2bfloat16(v.z), h3 = __float2bfloat16(v.w);
                            bf16 l0 = __float2bfloat16(v.x - __bfloat162float(h0));
                            bf16 l1 = __float2bfloat16(v.y - __bfloat162float(h1));
                            bf16 l2 = __float2bfloat16(v.z - __bfloat162float(h2));
                            bf16 l3 = __float2bfloat16(v.w - __bfloat162float(h3));
                            uint2 hw, lw;
                            hw.x = (uint32_t)__bfloat16_as_ushort(h0) |
                                   ((uint32_t)__bfloat16_as_ushort(h1) << 16);
                            hw.y = (uint32_t)__bfloat16_as_ushort(h2) |
                                   ((uint32_t)__bfloat16_as_ushort(h3) << 16);
                            lw.x = (uint32_t)__bfloat16_as_ushort(l0) |
                                   ((uint32_t)__bfloat16_as_ushort(l1) << 16);
                            lw.y = (uint32_t)__bfloat16_as_ushort(l2) |
                                   ((uint32_t)__bfloat16_as_ushort(l3) << 16);
                            *(uint2*)&Ch[orow * (size_t)N + c] = hw;
                            *(uint2*)&Cl[orow * (size_t)N + c] = lw;
                        } else {
                            size_t orow = SCATTER_C ? (size_t)g_perm[m0 + rowt + r]
                                                    : (size_t)(m0 + rowt + r);
                            *(float4*)&C[orow * (size_t)N + c] = v;
                        }
                    }
                }
                __syncwarp();
            }
        __syncthreads();   // staging aliases stage 0; next tm prefetch writes it
    }
}

// ---------------- launch ----------------------------------------------------
extern "C" void kernel_launch(void* const* d_in, const int* in_sizes, int n_in,
                              void* d_out, int out_size) {
    const float* x  = (const float*)d_in[0];
    const float* rw = (const float*)d_in[1];
    const float* rb = (const float*)d_in[2];
    const float* w1 = (const float*)d_in[3];
    const float* b1 = (const float*)d_in[4];
    const float* w2 = (const float*)d_in[5];
    const float* b2 = (const float*)d_in[6];
    float* out = (float*)d_out;

    void* p;
    cudaGetSymbolAddress(&p, g_xh);  bf16* xh  = (bf16*)p;
    cudaGetSymbolAddress(&p, g_xl);  bf16* xl  = (bf16*)p;
    cudaGetSymbolAddress(&p, g_w1h); bf16* w1h = (bf16*)p;
    cudaGetSymbolAddress(&p, g_w1l); bf16* w1l = (bf16*)p;
    cudaGetSymbolAddress(&p, g_w2h); bf16* w2h = (bf16*)p;
    cudaGetSymbolAddress(&p, g_w2l); bf16* w2l = (bf16*)p;
    cudaGetSymbolAddress(&p, g_Hh);  bf16* Hh  = (bf16*)p;
    cudaGetSymbolAddress(&p, g_Hl);  bf16* Hl  = (bf16*)p;

    cudaFuncSetAttribute(moe_gemm_b3<true,  false, true,  true>,
                         cudaFuncAttributeMaxDynamicSharedMemorySize, SMEM_BYTES);
    cudaFuncSetAttribute(moe_gemm_b3<false, true,  false, false>,
                         cudaFuncAttributeMaxDynamicSharedMemorySize, SMEM_BYTES);

    const long long main_elems = (long long)T_TOK * DIM;
    int write_loss = ((long long)out_size > main_elems) ? 1 : 0;

    zero_kernel<<<1, 32>>>();
    router_kernel<<<T_TOK / 8, 256>>>(x, rw, rb);
    setup_kernel<<<1, 1>>>(out + (size_t)T_TOK * DIM, write_loss);
    scatter_kernel<<<T_TOK / 256, 256>>>();

    // split operands into bf16 hi/lo pairs
    split_kernel<<<1024, 256>>>((const float4*)x,  (uint2*)xh,  (uint2*)xl,
                                (long)T_TOK * DIM / 4);
    split_kernel<<<2048, 256>>>((const float4*)w1, (uint2*)w1h, (uint2*)w1l,
                                (long)NE * DIM * FF / 4);
    split_kernel<<<2048, 256>>>((const float4*)w2, (uint2*)w2h, (uint2*)w2l,
                                (long)NE * DIM * FF / 4);

    // GEMM1: H(hi,lo) = split(relu(x[perm,:] @ w1[e] + b1[e]))   K=DIM, N=FF
    moe_gemm_b3<true, false, true, true>
        <<<dim3(FF / BN, 16, NE), 256, SMEM_BYTES>>>(
            xh, xl, w1h, w1l, b1, nullptr, Hh, Hl, DIM, FF);
    // GEMM2: out[perm,:] = H @ w2[e] + b2[e]                     K=FF, N=DIM
    moe_gemm_b3<false, true, false, false>
        <<<dim3(DIM / BN, 16, NE), 256, SMEM_BYTES>>>(
            Hh, Hl, w2h, w2l, b2, out, nullptr, nullptr, FF, DIM);
}

// round 6
// speedup vs baseline: 1.4964x; 1.1231x over previous
#include <cuda_runtime.h>
#include <cuda_bf16.h>
#include <mma.h>
#include <cstdint>

using namespace nvcuda;

// Problem constants (fixed: B=8,S=2048,D=1024,E=8,F=4096)
#define T_TOK 16384
#define DIM   1024
#define NE    8
#define FF    4096

typedef __nv_bfloat16 bf16;

// ---------------- scratch (device globals: allocation-free rule) ----------
__device__ int  g_counts[NE];
__device__ int  g_off[NE + 1];
__device__ int  g_cursor[NE];
__device__ int  g_perm[T_TOK];
__device__ int  g_expidx[T_TOK];
__device__ bf16 g_xh[(size_t)T_TOK * DIM];
__device__ bf16 g_xl[(size_t)T_TOK * DIM];
__device__ bf16 g_w1h[(size_t)NE * DIM * FF];
__device__ bf16 g_w1l[(size_t)NE * DIM * FF];
__device__ bf16 g_w2h[(size_t)NE * DIM * FF];
__device__ bf16 g_w2l[(size_t)NE * DIM * FF];
__device__ bf16 g_Hh[(size_t)T_TOK * FF];
__device__ bf16 g_Hl[(size_t)T_TOK * FF];

// ---------------- helpers ---------------------------------------------------
__device__ __forceinline__ void cpasync16(uint32_t dst, const void* src) {
    asm volatile("cp.async.cg.shared.global [%0], [%1], 16;\n"
                 :: "r"(dst), "l"(src));
}
__device__ __forceinline__ void cpasync_commit() {
    asm volatile("cp.async.commit_group;\n" ::: "memory");
}
template <int N>
__device__ __forceinline__ void cpasync_wait() {
    asm volatile("cp.async.wait_group %0;\n" :: "n"(N) : "memory");
}
__device__ __forceinline__ uint32_t smem_u32(const void* p) {
    uint32_t a;
    asm("{ .reg .u64 t; cvta.to.shared.u64 t, %1; cvt.u32.u64 %0, t; }"
        : "=r"(a) : "l"(p));
    return a;
}

// ---------------- small kernels -------------------------------------------
__global__ void zero_kernel() {
    if (threadIdx.x < NE) g_counts[threadIdx.x] = 0;
}

__global__ void router_kernel(const float* __restrict__ x,
                              const float* __restrict__ rw,
                              const float* __restrict__ rb) {
    int warp = (blockIdx.x * blockDim.x + threadIdx.x) >> 5;
    int lane = threadIdx.x & 31;
    if (warp >= T_TOK) return;
    const float* xr = x + (size_t)warp * DIM;
    float acc[NE];
#pragma unroll
    for (int e = 0; e < NE; e++) acc[e] = 0.f;
    for (int d = lane; d < DIM; d += 32) {
        float xv = xr[d];
        const float4* w4 = (const float4*)(rw + d * NE);
        float4 a = w4[0], b = w4[1];
        acc[0] += xv * a.x; acc[1] += xv * a.y; acc[2] += xv * a.z; acc[3] += xv * a.w;
        acc[4] += xv * b.x; acc[5] += xv * b.y; acc[6] += xv * b.z; acc[7] += xv * b.w;
    }
#pragma unroll
    for (int o = 16; o > 0; o >>= 1)
#pragma unroll
        for (int e = 0; e < NE; e++) acc[e] += __shfl_down_sync(0xffffffffu, acc[e], o);
    if (lane == 0) {
        int bi = 0;
        float bv = acc[0] + rb[0];
#pragma unroll
        for (int e = 1; e < NE; e++) {
            float v = acc[e] + rb[e];
            if (v > bv) { bv = v; bi = e; }   // strict > == first max (jnp.argmax)
        }
        g_expidx[warp] = bi;
        atomicAdd(&g_counts[bi], 1);
    }
}

__global__ void setup_kernel(float* out_loss, int write_loss) {
    int off = 0;
    for (int e = 0; e < NE; e++) { g_off[e] = off; g_cursor[e] = off; off += g_counts[e]; }
    g_off[NE] = off;
    if (write_loss) {
        float lb = 0.f;
        for (int e = 0; e < NE; e++) {
            float u = (float)g_counts[e] / (float)T_TOK - 1.0f / NE;
            lb += u * u;
        }
        *out_loss = lb / NE;
    }
}

__global__ void scatter_kernel() {
    int t = blockIdx.x * blockDim.x + threadIdx.x;
    if (t >= T_TOK) return;
    int e = g_expidx[t];
    int p = atomicAdd(&g_cursor[e], 1);
    g_perm[p] = t;
}

// fp32 -> (hi, lo) bf16 split, 4 elems/thread-iter
__global__ void split_kernel(const float4* __restrict__ in,
                             uint2* __restrict__ hi, uint2* __restrict__ lo,
                             long n4) {
    long i = (long)blockIdx.x * blockDim.x + threadIdx.x;
    long stride = (long)gridDim.x * blockDim.x;
    for (; i < n4; i += stride) {
        float4 v = in[i];
        bf16 h0 = __float2bfloat16(v.x), h1 = __float2bfloat16(v.y);
        bf16 h2 = __float2bfloat16(v.z), h3 = __float2bfloat16(v.w);
        bf16 l0 = __float2bfloat16(v.x - __bfloat162float(h0));
        bf16 l1 = __float2bfloat16(v.y - __bfloat162float(h1));
        bf16 l2 = __float2bfloat16(v.z - __bfloat162float(h2));
        bf16 l3 = __float2bfloat16(v.w - __bfloat162float(h3));
        uint2 hw, lw;
        hw.x = (uint32_t)__bfloat16_as_ushort(h0) |
               ((uint32_t)__bfloat16_as_ushort(h1) << 16);
        hw.y = (uint32_t)__bfloat16_as_ushort(h2) |
               ((uint32_t)__bfloat16_as_ushort(h3) << 16);
        lw.x = (uint32_t)__bfloat16_as_ushort(l0) |
               ((uint32_t)__bfloat16_as_ushort(l1) << 16);
        lw.y = (uint32_t)__bfloat16_as_ushort(l2) |
               ((uint32_t)__bfloat16_as_ushort(l3) << 16);
        hi[i] = hw;
        lo[i] = lw;
    }
}

// ---------------- grouped GEMM: bf16x3 compensated (real HMMA) --------------
// C = act( (Ah+Al) @ (Wh+Wl) + bias )  ~=  Ah@Wh + Ah@Wl + Al@Wh  (fp32 accum)
// CTA 128x256x32, 512 threads = 16 warps (2M x 8N), warp tile 64x32.
// 3-stage cp.async pipeline (prefetch distance 2, one sync per k-tile).
constexpr int BM = 128, BN = 256, BK = 32;
constexpr int THREADS = 512;
constexpr int ALD = 40;                    // bf16 elems per A smem row (80 B)
constexpr int BLD = 264;                   // bf16 elems per B smem row (528 B)
constexpr int A_T = BM * ALD * 2;          // 10240 B per A tile (h or l)
constexpr int B_T = BK * BLD * 2;          // 16896 B per B tile (h or l)
constexpr int STAGE = 2 * A_T + 2 * B_T;   // 54272 B
constexpr int NSTAGE = 3;
constexpr int SMEM_BYTES = NSTAGE * STAGE + 256;   // ~163 KB

typedef wmma::fragment<wmma::matrix_a, 16, 16, 16, bf16, wmma::row_major> FragA;
typedef wmma::fragment<wmma::matrix_b, 16, 16, 16, bf16, wmma::row_major> FragB;
typedef wmma::fragment<wmma::accumulator, 16, 16, 16, float> FragC;

template <bool GATHER_A, bool SCATTER_C, bool RELU, bool SPLIT_OUT>
__global__ __launch_bounds__(THREADS, 1)
void moe_gemm_b3(const bf16* __restrict__ Ah, const bf16* __restrict__ Al,
                 const bf16* __restrict__ Wh, const bf16* __restrict__ Wl,
                 const float* __restrict__ bias, float* __restrict__ C,
                 bf16* __restrict__ Ch, bf16* __restrict__ Cl,
                 int K, int N) {
    extern __shared__ __align__(16) char smem[];
    const uint32_t base = smem_u32(smem);

    const int tid  = threadIdx.x;
    const int warp = tid >> 5;
    const int lane = tid & 31;
    const int wm = warp >> 3;    // 2 warps over M (64 rows)
    const int wn = warp & 7;     // 8 warps over N (32 cols)

    const int e    = blockIdx.z;
    const int m0   = g_off[e];
    const int rows = g_off[e + 1] - m0;
    const int n0   = blockIdx.x * BN;
    const bf16* Whe = Wh + (size_t)e * K * N;
    const bf16* Wle = Wl + (size_t)e * K * N;
    const float* be = bias + (size_t)e * N;
    const int ktiles = K / BK;

    // cp.async per-thread slots (512 threads)
    const int a_r = tid >> 2;          // A row 0..127, one per thread
    const int a_c = tid & 3;           // 16B chunk (8 bf16) in BK=32
    const int b_r = tid >> 5;          // B rows b_r, b_r+16
    const int b_c = tid & 31;          // 16B chunk in BN=256
    const uint32_t aoff = (uint32_t)a_r * 80u + a_c * 16u;

    for (int tm = blockIdx.y; tm * BM < rows; tm += gridDim.y) {
        const int rowt = tm * BM;

        int p = m0 + min(rowt + a_r, rows - 1);
        size_t asrcrow = GATHER_A ? (size_t)g_perm[p] * K : (size_t)p * K;
        const bf16* aph = Ah + asrcrow;
        const bf16* apl = Al + asrcrow;

        FragC fc[4][2];
#pragma unroll
        for (int i = 0; i < 4; i++)
#pragma unroll
            for (int j = 0; j < 2; j++) wmma::fill_fragment(fc[i][j], 0.f);

        // prefetch k-tiles 0,1
#pragma unroll
        for (int pk = 0; pk < 2; pk++) {
            uint32_t sb = base + pk * STAGE;
            int kb = pk * BK;
            cpasync16(sb + aoff,       aph + kb + a_c * 8);
            cpasync16(sb + A_T + aoff, apl + kb + a_c * 8);
#pragma unroll
            for (int q = 0; q < 2; q++) {
                uint32_t boff = (uint32_t)(b_r + 16 * q) * 528u + b_c * 16u;
                size_t src = (size_t)(kb + b_r + 16 * q) * N + n0 + b_c * 8;
                cpasync16(sb + 2 * A_T + boff,       Whe + src);
                cpasync16(sb + 2 * A_T + B_T + boff, Wle + src);
            }
            cpasync_commit();
        }

        for (int kt = 0; kt < ktiles; kt++) {
            if (kt < ktiles - 1) cpasync_wait<1>();
            else                 cpasync_wait<0>();
            __syncthreads();

            // prefetch kt+2 into stage (kt+2)%3
            const int nk = kt + 2;
            if (nk < ktiles) {
                const int s = nk - (nk / 3) * 3;
                uint32_t sb = base + s * STAGE;
                int kb = nk * BK;
                cpasync16(sb + aoff,       aph + kb + a_c * 8);
                cpasync16(sb + A_T + aoff, apl + kb + a_c * 8);
#pragma unroll
                for (int q = 0; q < 2; q++) {
                    uint32_t boff = (uint32_t)(b_r + 16 * q) * 528u + b_c * 16u;
                    size_t src = (size_t)(kb + b_r + 16 * q) * N + n0 + b_c * 8;
                    cpasync16(sb + 2 * A_T + boff,       Whe + src);
                    cpasync16(sb + 2 * A_T + B_T + boff, Wle + src);
                }
                cpasync_commit();
            }

            const int cur = kt - (kt / 3) * 3;
            const bf16* Ahs = (const bf16*)(smem + cur * STAGE);
            const bf16* Als = (const bf16*)(smem + cur * STAGE + A_T);
            const bf16* Bhs = (const bf16*)(smem + cur * STAGE + 2 * A_T);
            const bf16* Bls = (const bf16*)(smem + cur * STAGE + 2 * A_T + B_T);

#pragma unroll
            for (int kk = 0; kk < BK / 16; kk++) {
                // B fragments first (stay live), A fragments per-i (short live)
                FragB fbh[2], fbl[2];
#pragma unroll
                for (int j = 0; j < 2; j++) {
                    const int c = wn * 32 + j * 16;
                    wmma::load_matrix_sync(fbh[j], Bhs + kk * 16 * BLD + c, BLD);
                    wmma::load_matrix_sync(fbl[j], Bls + kk * 16 * BLD + c, BLD);
                }
#pragma unroll
                for (int i = 0; i < 4; i++) {
                    const int r = wm * 64 + i * 16;
                    FragA fah, fal;
                    wmma::load_matrix_sync(fah, Ahs + r * ALD + kk * 16, ALD);
                    wmma::load_matrix_sync(fal, Als + r * ALD + kk * 16, ALD);
#pragma unroll
                    for (int j = 0; j < 2; j++) {
                        wmma::mma_sync(fc[i][j], fah, fbh[j], fc[i][j]);
                        wmma::mma_sync(fc[i][j], fah, fbl[j], fc[i][j]);
                        wmma::mma_sync(fc[i][j], fal, fbh[j], fc[i][j]);
                    }
                }
            }
        }

        __syncthreads();   // done with pipeline smem; reuse for staging

        // epilogue: per-warp 16x16 staging (fp32), bias(+relu), store
        float* stage = (float*)(smem) + warp * (16 * 20);
#pragma unroll
        for (int i = 0; i < 4; i++)
#pragma unroll
            for (int j = 0; j < 2; j++) {
                wmma::store_matrix_sync(stage, fc[i][j], 20, wmma::mem_row_major);
                __syncwarp();
#pragma unroll
                for (int t = 0; t < 2; t++) {
                    int idx = lane + 32 * t;        // 64 slots: 16 rows x 4 f4
                    int rr = idx >> 2, cc4 = idx & 3;
                    int r = wm * 64 + i * 16 + rr;
                    int c = n0 + wn * 32 + j * 16 + cc4 * 4;
                    if (rowt + r < rows) {
                        float4 v = *(float4*)&stage[rr * 20 + cc4 * 4];
                        float4 b = *(const float4*)&be[c];
                        v.x += b.x; v.y += b.y; v.z += b.z; v.w += b.w;
                        if (RELU) {
                            v.x = fmaxf(v.x, 0.f); v.y = fmaxf(v.y, 0.f);
                            v.z = fmaxf(v.z, 0.f); v.w = fmaxf(v.w, 0.f);
                        }
                        if (SPLIT_OUT) {
                            size_t orow = (size_t)(m0 + rowt + r);
                            bf16 h0 = __float2bfloat16(v.x), h1 = __float2bfloat16(v.y);
                            bf16 h2 = __float2bfloat16(v.z), h3 = __float2bfloat16(v.w);
                            bf16 l0 = __float2bfloat16(v.x - __bfloat162float(h0));
                            bf16 l1 = __float2bfloat16(v.y - __bfloat162float(h1));
                            bf16 l2 = __float2bfloat16(v.z - __bfloat162float(h2));
                            bf16 l3 = __float2bfloat16(v.w - __bfloat162float(h3));
                            uint2 hw, lw;
                            hw.x = (uint32_t)__bfloat16_as_ushort(h0) |
                                   ((uint32_t)__bfloat16_as_ushort(h1) << 16);
                            hw.y = (uint32_t)__bfloat16_as_ushort(h2) |
                                   ((uint32_t)__bfloat16_as_ushort(h3) << 16);
                            lw.x = (uint32_t)__bfloat16_as_ushort(l0) |
                                   ((uint32_t)__bfloat16_as_ushort(l1) << 16);
                            lw.y = (uint32_t)__bfloat16_as_ushort(l2) |
                                   ((uint32_t)__bfloat16_as_ushort(l3) << 16);
                            *(uint2*)&Ch[orow * (size_t)N + c] = hw;
                            *(uint2*)&Cl[orow * (size_t)N + c] = lw;
                        } else {
                            size_t orow = SCATTER_C ? (size_t)g_perm[m0 + rowt + r]
                                                    : (size_t)(m0 + rowt + r);
                            *(float4*)&C[orow * (size_t)N + c] = v;
                        }
                    }
                }
                __syncwarp();
            }
        __syncthreads();   // staging aliases stage 0; next tm prefetch writes it
    }
}

// ---------------- launch ----------------------------------------------------
extern "C" void kernel_launch(void* const* d_in, const int* in_sizes, int n_in,
                              void* d_out, int out_size) {
    const float* x  = (const float*)d_in[0];
    const float* rw = (const float*)d_in[1];
    const float* rb = (const float*)d_in[2];
    const float* w1 = (const float*)d_in[3];
    const float* b1 = (const float*)d_in[4];
    const float* w2 = (const float*)d_in[5];
    const float* b2 = (const float*)d_in[6];
    float* out = (float*)d_out;

    void* p;
    cudaGetSymbolAddress(&p, g_xh);  bf16* xh  = (bf16*)p;
    cudaGetSymbolAddress(&p, g_xl);  bf16* xl  = (bf16*)p;
    cudaGetSymbolAddress(&p, g_w1h); bf16* w1h = (bf16*)p;
    cudaGetSymbolAddress(&p, g_w1l); bf16* w1l = (bf16*)p;
    cudaGetSymbolAddress(&p, g_w2h); bf16* w2h = (bf16*)p;
    cudaGetSymbolAddress(&p, g_w2l); bf16* w2l = (bf16*)p;
    cudaGetSymbolAddress(&p, g_Hh);  bf16* Hh  = (bf16*)p;
    cudaGetSymbolAddress(&p, g_Hl);  bf16* Hl  = (bf16*)p;

    cudaFuncSetAttribute(moe_gemm_b3<true,  false, true,  true>,
                         cudaFuncAttributeMaxDynamicSharedMemorySize, SMEM_BYTES);
    cudaFuncSetAttribute(moe_gemm_b3<false, true,  false, false>,
                         cudaFuncAttributeMaxDynamicSharedMemorySize, SMEM_BYTES);

    const long long main_elems = (long long)T_TOK * DIM;
    int write_loss = ((long long)out_size > main_elems) ? 1 : 0;

    zero_kernel<<<1, 32>>>();
    router_kernel<<<T_TOK / 8, 256>>>(x, rw, rb);
    setup_kernel<<<1, 1>>>(out + (size_t)T_TOK * DIM, write_loss);
    scatter_kernel<<<T_TOK / 256, 256>>>();

    // split operands into bf16 hi/lo pairs
    split_kernel<<<1024, 256>>>((const float4*)x,  (uint2*)xh,  (uint2*)xl,
                                (long)T_TOK * DIM / 4);
    split_kernel<<<2048, 256>>>((const float4*)w1, (uint2*)w1h, (uint2*)w1l,
                                (long)NE * DIM * FF / 4);
    split_kernel<<<2048, 256>>>((const float4*)w2, (uint2*)w2h, (uint2*)w2l,
                                (long)NE * DIM * FF / 4);

    // GEMM1: H(hi,lo) = split(relu(x[perm,:] @ w1[e] + b1[e]))   K=DIM, N=FF
    moe_gemm_b3<true, false, true, true>
        <<<dim3(FF / BN, 16, NE), THREADS, SMEM_BYTES>>>(
            xh, xl, w1h, w1l, b1, nullptr, Hh, Hl, DIM, FF);
    // GEMM2: out[perm,:] = H @ w2[e] + b2[e]                     K=FF, N=DIM
    moe_gemm_b3<false, true, false, false>
        <<<dim3(DIM / BN, 16, NE), THREADS, SMEM_BYTES>>>(
            Hh, Hl, w2h, w2l, b2, out, nullptr, nullptr, FF, DIM);
}

// round 7
// speedup vs baseline: 2.4655x; 1.6476x over previous
#include <cuda_runtime.h>
#include <cuda_fp16.h>
#include <mma.h>
#include <cstdint>

using namespace nvcuda;

// Problem constants (fixed: B=8,S=2048,D=1024,E=8,F=4096)
#define T_TOK 16384
#define DIM   1024
#define NE    8
#define FF    4096

typedef __half fp16;

// ---------------- scratch (device globals: allocation-free rule) ----------
__device__ int  g_counts[NE];
__device__ int  g_off[NE + 1];
__device__ int  g_cursor[NE];
__device__ int  g_perm[T_TOK];
__device__ int  g_expidx[T_TOK];
__device__ fp16 g_xh[(size_t)T_TOK * DIM];        // x in fp16 (single)
__device__ fp16 g_w1h[(size_t)NE * DIM * FF];     // w1 hi
__device__ fp16 g_w1l[(size_t)NE * DIM * FF];     // w1 lo
__device__ fp16 g_w2h[(size_t)NE * DIM * FF];     // w2 hi
__device__ fp16 g_w2l[(size_t)NE * DIM * FF];     // w2 lo
__device__ fp16 g_Hh[(size_t)T_TOK * FF];         // hidden in fp16 (single)

// ---------------- helpers ---------------------------------------------------
__device__ __forceinline__ void cpasync16(uint32_t dst, const void* src) {
    asm volatile("cp.async.cg.shared.global [%0], [%1], 16;\n"
                 :: "r"(dst), "l"(src));
}
__device__ __forceinline__ void cpasync_commit() {
    asm volatile("cp.async.commit_group;\n" ::: "memory");
}
template <int N>
__device__ __forceinline__ void cpasync_wait() {
    asm volatile("cp.async.wait_group %0;\n" :: "n"(N) : "memory");
}
__device__ __forceinline__ uint32_t smem_u32(const void* p) {
    uint32_t a;
    asm("{ .reg .u64 t; cvta.to.shared.u64 t, %1; cvt.u32.u64 %0, t; }"
        : "=r"(a) : "l"(p));
    return a;
}

// ---------------- small kernels -------------------------------------------
// One warp per token: logits = x_t @ router_w + router_b, argmax (first max).
__global__ void router_kernel(const float* __restrict__ x,
                              const float* __restrict__ rw,
                              const float* __restrict__ rb) {
    int warp = (blockIdx.x * blockDim.x + threadIdx.x) >> 5;
    int lane = threadIdx.x & 31;
    if (warp >= T_TOK) return;
    const float* xr = x + (size_t)warp * DIM;
    float acc[NE];
#pragma unroll
    for (int e = 0; e < NE; e++) acc[e] = 0.f;
    for (int d = lane; d < DIM; d += 32) {
        float xv = xr[d];
        const float4* w4 = (const float4*)(rw + d * NE);
        float4 a = w4[0], b = w4[1];
        acc[0] += xv * a.x; acc[1] += xv * a.y; acc[2] += xv * a.z; acc[3] += xv * a.w;
        acc[4] += xv * b.x; acc[5] += xv * b.y; acc[6] += xv * b.z; acc[7] += xv * b.w;
    }
#pragma unroll
    for (int o = 16; o > 0; o >>= 1)
#pragma unroll
        for (int e = 0; e < NE; e++) acc[e] += __shfl_down_sync(0xffffffffu, acc[e], o);
    if (lane == 0) {
        int bi = 0;
        float bv = acc[0] + rb[0];
#pragma unroll
        for (int e = 1; e < NE; e++) {
            float v = acc[e] + rb[e];
            if (v > bv) { bv = v; bi = e; }   // strict > == first max (jnp.argmax)
        }
        g_expidx[warp] = bi;
    }
}

// Single block: count experts, prefix offsets, cursors, lb_loss.
__global__ void setup_kernel(float* out_loss, int write_loss) {
    __shared__ int sc[NE];
    const int tid = threadIdx.x;   // 256
    if (tid < NE) sc[tid] = 0;
    __syncthreads();
    int cnt[NE];
#pragma unroll
    for (int e = 0; e < NE; e++) cnt[e] = 0;
    for (int t = tid; t < T_TOK; t += 256) {
        int ei = g_expidx[t];
#pragma unroll
        for (int e = 0; e < NE; e++) cnt[e] += (ei == e);
    }
#pragma unroll
    for (int e = 0; e < NE; e++)
        if (cnt[e]) atomicAdd(&sc[e], cnt[e]);
    __syncthreads();
    if (tid == 0) {
        int off = 0;
        for (int e = 0; e < NE; e++) {
            g_counts[e] = sc[e];
            g_off[e] = off; g_cursor[e] = off; off += sc[e];
        }
        g_off[NE] = off;
        if (write_loss) {
            float lb = 0.f;
            for (int e = 0; e < NE; e++) {
                float u = (float)sc[e] / (float)T_TOK - 1.0f / NE;
                lb += u * u;
            }
            *out_loss = lb / NE;
        }
    }
}

__global__ void scatter_kernel() {
    int t = blockIdx.x * blockDim.x + threadIdx.x;
    if (t >= T_TOK) return;
    int e = g_expidx[t];
    int p = atomicAdd(&g_cursor[e], 1);
    g_perm[p] = t;
}

// Fused conversion: z=0 -> x to fp16 (single); z=1/2 -> w1/w2 to (hi,lo) pairs.
__global__ void split_all_kernel(const float4* __restrict__ x,
                                 const float4* __restrict__ w1,
                                 const float4* __restrict__ w2,
                                 uint2* __restrict__ xh,
                                 uint2* __restrict__ w1h, uint2* __restrict__ w1l,
                                 uint2* __restrict__ w2h, uint2* __restrict__ w2l) {
    const int z = blockIdx.z;
    const float4* src = (z == 0) ? x : (z == 1) ? w1 : w2;
    uint2* dh = (z == 0) ? xh : (z == 1) ? w1h : w2h;
    uint2* dl = (z == 0) ? nullptr : (z == 1) ? w1l : w2l;
    const long n4 = (z == 0) ? (long)T_TOK * DIM / 4 : (long)NE * DIM * FF / 4;
    long i = (long)blockIdx.x * blockDim.x + threadIdx.x;
    const long stride = (long)gridDim.x * blockDim.x;
    for (; i < n4; i += stride) {
        float4 v = src[i];
        __half2 h01 = __floats2half2_rn(v.x, v.y);
        __half2 h23 = __floats2half2_rn(v.z, v.w);
        uint2 hw;
        hw.x = *(uint32_t*)&h01; hw.y = *(uint32_t*)&h23;
        dh[i] = hw;
        if (dl) {
            float2 f01 = __half22float2(h01), f23 = __half22float2(h23);
            __half2 l01 = __floats2half2_rn(v.x - f01.x, v.y - f01.y);
            __half2 l23 = __floats2half2_rn(v.z - f23.x, v.w - f23.y);
            uint2 lw;
            lw.x = *(uint32_t*)&l01; lw.y = *(uint32_t*)&l23;
            dl[i] = lw;
        }
    }
}

// ---------------- grouped GEMM: fp16 2-product compensated ------------------
// C = act( A @ (Wh + Wl) + bias ),  A fp16 (single), W = fp16 hi/lo pair.
// CTA 128x256x32, 512 threads = 16 warps (2M x 8N), warp tile 64x32.
// 3-stage cp.async pipeline (prefetch distance 2, one sync per k-tile).
constexpr int BM = 128, BN = 256, BK = 32;
constexpr int THREADS = 512;
constexpr int ALD = 40;                    // fp16 per A smem row (80 B)
constexpr int BLD = 264;                   // fp16 per B smem row (528 B)
constexpr int A_T = BM * ALD * 2;          // 10240 B
constexpr int B_T = BK * BLD * 2;          // 16896 B per B tile (h or l)
constexpr int STAGE = A_T + 2 * B_T;       // 44032 B
constexpr int NSTAGE = 3;
constexpr int SMEM_BYTES = NSTAGE * STAGE + 256;   // ~132.3 KB

typedef wmma::fragment<wmma::matrix_a, 16, 16, 16, fp16, wmma::row_major> FragA;
typedef wmma::fragment<wmma::matrix_b, 16, 16, 16, fp16, wmma::row_major> FragB;
typedef wmma::fragment<wmma::accumulator, 16, 16, 16, float> FragC;

template <bool GATHER_A, bool SCATTER_C, bool RELU, bool HALF_OUT>
__global__ __launch_bounds__(THREADS, 1)
void moe_gemm_f2(const fp16* __restrict__ A,
                 const fp16* __restrict__ Wh, const fp16* __restrict__ Wl,
                 const float* __restrict__ bias, float* __restrict__ C,
                 fp16* __restrict__ Ch, int K, int N) {
    extern __shared__ __align__(16) char smem[];
    const uint32_t base = smem_u32(smem);

    const int tid  = threadIdx.x;
    const int warp = tid >> 5;
    const int lane = tid & 31;
    const int wm = warp >> 3;    // 2 warps over M (64 rows)
    const int wn = warp & 7;     // 8 warps over N (32 cols)

    const int e    = blockIdx.z;
    const int m0   = g_off[e];
    const int rows = g_off[e + 1] - m0;
    const int n0   = blockIdx.x * BN;
    const fp16* Whe = Wh + (size_t)e * K * N;
    const fp16* Wle = Wl + (size_t)e * K * N;
    const float* be = bias + (size_t)e * N;
    const int ktiles = K / BK;

    // cp.async per-thread slots (512 threads)
    const int a_r = tid >> 2;          // A row 0..127
    const int a_c = tid & 3;           // 16B chunk (8 fp16) in BK=32
    const int b_r = tid >> 5;          // B rows b_r, b_r+16
    const int b_c = tid & 31;          // 16B chunk in BN=256
    const uint32_t aoff = (uint32_t)a_r * 80u + a_c * 16u;

    for (int tm = blockIdx.y; tm * BM < rows; tm += gridDim.y) {
        const int rowt = tm * BM;

        int p = m0 + min(rowt + a_r, rows - 1);
        const fp16* aph = A + (GATHER_A ? (size_t)g_perm[p] * K : (size_t)p * K);

        FragC fc[4][2];
#pragma unroll
        for (int i = 0; i < 4; i++)
#pragma unroll
            for (int j = 0; j < 2; j++) wmma::fill_fragment(fc[i][j], 0.f);

        // prefetch k-tiles 0,1
#pragma unroll
        for (int pk = 0; pk < 2; pk++) {
            uint32_t sb = base + pk * STAGE;
            int kb = pk * BK;
            cpasync16(sb + aoff, aph + kb + a_c * 8);
#pragma unroll
            for (int q = 0; q < 2; q++) {
                uint32_t boff = (uint32_t)(b_r + 16 * q) * 528u + b_c * 16u;
                size_t src = (size_t)(kb + b_r + 16 * q) * N + n0 + b_c * 8;
                cpasync16(sb + A_T + boff,       Whe + src);
                cpasync16(sb + A_T + B_T + boff, Wle + src);
            }
            cpasync_commit();
        }

        for (int kt = 0; kt < ktiles; kt++) {
            if (kt < ktiles - 1) cpasync_wait<1>();
            else                 cpasync_wait<0>();
            __syncthreads();

            // prefetch kt+2 into stage (kt+2)%3
            const int nk = kt + 2;
            if (nk < ktiles) {
                const int s = nk - (nk / 3) * 3;
                uint32_t sb = base + s * STAGE;
                int kb = nk * BK;
                cpasync16(sb + aoff, aph + kb + a_c * 8);
#pragma unroll
                for (int q = 0; q < 2; q++) {
                    uint32_t boff = (uint32_t)(b_r + 16 * q) * 528u + b_c * 16u;
                    size_t src = (size_t)(kb + b_r + 16 * q) * N + n0 + b_c * 8;
                    cpasync16(sb + A_T + boff,       Whe + src);
                    cpasync16(sb + A_T + B_T + boff, Wle + src);
                }
                cpasync_commit();
            }

            const int cur = kt - (kt / 3) * 3;
            const fp16* As  = (const fp16*)(smem + cur * STAGE);
            const fp16* Bhs = (const fp16*)(smem + cur * STAGE + A_T);
            const fp16* Bls = (const fp16*)(smem + cur * STAGE + A_T + B_T);

#pragma unroll
            for (int kk = 0; kk < BK / 16; kk++) {
                FragB fbh[2], fbl[2];
#pragma unroll
                for (int j = 0; j < 2; j++) {
                    const int c = wn * 32 + j * 16;
                    wmma::load_matrix_sync(fbh[j], Bhs + kk * 16 * BLD + c, BLD);
                    wmma::load_matrix_sync(fbl[j], Bls + kk * 16 * BLD + c, BLD);
                }
#pragma unroll
                for (int i = 0; i < 4; i++) {
                    const int r = wm * 64 + i * 16;
                    FragA fa;
                    wmma::load_matrix_sync(fa, As + r * ALD + kk * 16, ALD);
#pragma unroll
                    for (int j = 0; j < 2; j++) {
                        wmma::mma_sync(fc[i][j], fa, fbh[j], fc[i][j]);
                        wmma::mma_sync(fc[i][j], fa, fbl[j], fc[i][j]);
                    }
                }
            }
        }

        __syncthreads();   // done with pipeline smem; reuse for staging

        // epilogue: per-warp 16x16 staging (fp32), bias(+relu), store
        float* stage = (float*)(smem) + warp * (16 * 20);
#pragma unroll
        for (int i = 0; i < 4; i++)
#pragma unroll
            for (int j = 0; j < 2; j++) {
                wmma::store_matrix_sync(stage, fc[i][j], 20, wmma::mem_row_major);
                __syncwarp();
#pragma unroll
                for (int t = 0; t < 2; t++) {
                    int idx = lane + 32 * t;        // 64 slots: 16 rows x 4 f4
                    int rr = idx >> 2, cc4 = idx & 3;
                    int r = wm * 64 + i * 16 + rr;
                    int c = n0 + wn * 32 + j * 16 + cc4 * 4;
                    if (rowt + r < rows) {
                        float4 v = *(float4*)&stage[rr * 20 + cc4 * 4];
                        float4 b = *(const float4*)&be[c];
                        v.x += b.x; v.y += b.y; v.z += b.z; v.w += b.w;
                        if (RELU) {
                            v.x = fmaxf(v.x, 0.f); v.y = fmaxf(v.y, 0.f);
                            v.z = fmaxf(v.z, 0.f); v.w = fmaxf(v.w, 0.f);
                        }
                        if (HALF_OUT) {
                            size_t orow = (size_t)(m0 + rowt + r);
                            __half2 p0 = __floats2half2_rn(v.x, v.y);
                            __half2 p1 = __floats2half2_rn(v.z, v.w);
                            uint2 hw;
                            hw.x = *(uint32_t*)&p0; hw.y = *(uint32_t*)&p1;
                            *(uint2*)&Ch[orow * (size_t)N + c] = hw;
                        } else {
                            size_t orow = SCATTER_C ? (size_t)g_perm[m0 + rowt + r]
                                                    : (size_t)(m0 + rowt + r);
                            *(float4*)&C[orow * (size_t)N + c] = v;
                        }
                    }
                }
                __syncwarp();
            }
        __syncthreads();   // staging aliases stage 0; next tm prefetch writes it
    }
}

// ---------------- launch ----------------------------------------------------
extern "C" void kernel_launch(void* const* d_in, const int* in_sizes, int n_in,
                              void* d_out, int out_size) {
    const float* x  = (const float*)d_in[0];
    const float* rw = (const float*)d_in[1];
    const float* rb = (const float*)d_in[2];
    const float* w1 = (const float*)d_in[3];
    const float* b1 = (const float*)d_in[4];
    const float* w2 = (const float*)d_in[5];
    const float* b2 = (const float*)d_in[6];
    float* out = (float*)d_out;

    void* p;
    cudaGetSymbolAddress(&p, g_xh);  fp16* xh  = (fp16*)p;
    cudaGetSymbolAddress(&p, g_w1h); fp16* w1h = (fp16*)p;
    cudaGetSymbolAddress(&p, g_w1l); fp16* w1l = (fp16*)p;
    cudaGetSymbolAddress(&p, g_w2h); fp16* w2h = (fp16*)p;
    cudaGetSymbolAddress(&p, g_w2l); fp16* w2l = (fp16*)p;
    cudaGetSymbolAddress(&p, g_Hh);  fp16* Hh  = (fp16*)p;

    cudaFuncSetAttribute(moe_gemm_f2<true,  false, true,  true>,
                         cudaFuncAttributeMaxDynamicSharedMemorySize, SMEM_BYTES);
    cudaFuncSetAttribute(moe_gemm_f2<false, true,  false, false>,
                         cudaFuncAttributeMaxDynamicSharedMemorySize, SMEM_BYTES);

    const long long main_elems = (long long)T_TOK * DIM;
    int write_loss = ((long long)out_size > main_elems) ? 1 : 0;

    // 6 launches total so the ncu window (-s 5 -c 1) lands on a GEMM.
    router_kernel<<<T_TOK / 8, 256>>>(x, rw, rb);                      // 1
    setup_kernel<<<1, 256>>>(out + (size_t)T_TOK * DIM, write_loss);   // 2
    scatter_kernel<<<T_TOK / 256, 256>>>();                            // 3
    split_all_kernel<<<dim3(1024, 1, 3), 256>>>(                       // 4
        (const float4*)x, (const float4*)w1, (const float4*)w2,
        (uint2*)xh, (uint2*)w1h, (uint2*)w1l, (uint2*)w2h, (uint2*)w2l);

    // GEMM1: Hh = fp16(relu(x[perm,:] @ w1[e] + b1[e]))   K=DIM, N=FF
    moe_gemm_f2<true, false, true, true>                               // 5
        <<<dim3(FF / BN, 16, NE), THREADS, SMEM_BYTES>>>(
            xh, w1h, w1l, b1, nullptr, Hh, DIM, FF);
    // GEMM2: out[perm,:] = Hh @ w2[e] + b2[e]             K=FF, N=DIM
    moe_gemm_f2<false, true, false, false>                             // 6
        <<<dim3(DIM / BN, 16, NE), THREADS, SMEM_BYTES>>>(
            Hh, w2h, w2l, b2, out, nullptr, FF, DIM);
}

// round 8
// speedup vs baseline: 3.8987x; 1.5813x over previous
#include <cuda_runtime.h>
#include <cuda_fp16.h>
#include <mma.h>
#include <cstdint>

using namespace nvcuda;

// Problem constants (fixed: B=8,S=2048,D=1024,E=8,F=4096)
#define T_TOK 16384
#define DIM   1024
#define NE    8
#define FF    4096

typedef __half fp16;

// ---------------- scratch (device globals: allocation-free rule) ----------
__device__ int  g_off[NE + 1];
__device__ int  g_perm[T_TOK];
__device__ int  g_expidx[T_TOK];
__device__ fp16 g_xh[(size_t)T_TOK * DIM];        // x in fp16
__device__ fp16 g_w1h[(size_t)NE * DIM * FF];     // w1 in fp16
__device__ fp16 g_w2h[(size_t)NE * DIM * FF];     // w2 in fp16
__device__ fp16 g_Hh[(size_t)T_TOK * FF];         // hidden in fp16

// ---------------- helpers ---------------------------------------------------
__device__ __forceinline__ void cpasync16(uint32_t dst, const void* src) {
    asm volatile("cp.async.cg.shared.global [%0], [%1], 16;\n"
                 :: "r"(dst), "l"(src));
}
__device__ __forceinline__ void cpasync_commit() {
    asm volatile("cp.async.commit_group;\n" ::: "memory");
}
template <int N>
__device__ __forceinline__ void cpasync_wait() {
    asm volatile("cp.async.wait_group %0;\n" :: "n"(N) : "memory");
}
__device__ __forceinline__ uint32_t smem_u32(const void* p) {
    uint32_t a;
    asm("{ .reg .u64 t; cvta.to.shared.u64 t, %1; cvt.u32.u64 %0, t; }"
        : "=r"(a) : "l"(p));
    return a;
}

// ---------------- small kernels -------------------------------------------
// One warp per token: logits = x_t @ router_w + router_b, argmax (first max).
__global__ void router_kernel(const float* __restrict__ x,
                              const float* __restrict__ rw,
                              const float* __restrict__ rb) {
    int warp = (blockIdx.x * blockDim.x + threadIdx.x) >> 5;
    int lane = threadIdx.x & 31;
    if (warp >= T_TOK) return;
    const float* xr = x + (size_t)warp * DIM;
    float acc[NE];
#pragma unroll
    for (int e = 0; e < NE; e++) acc[e] = 0.f;
    for (int d = lane; d < DIM; d += 32) {
        float xv = xr[d];
        const float4* w4 = (const float4*)(rw + d * NE);
        float4 a = w4[0], b = w4[1];
        acc[0] += xv * a.x; acc[1] += xv * a.y; acc[2] += xv * a.z; acc[3] += xv * a.w;
        acc[4] += xv * b.x; acc[5] += xv * b.y; acc[6] += xv * b.z; acc[7] += xv * b.w;
    }
#pragma unroll
    for (int o = 16; o > 0; o >>= 1)
#pragma unroll
        for (int e = 0; e < NE; e++) acc[e] += __shfl_down_sync(0xffffffffu, acc[e], o);
    if (lane == 0) {
        int bi = 0;
        float bv = acc[0] + rb[0];
#pragma unroll
        for (int e = 1; e < NE; e++) {
            float v = acc[e] + rb[e];
            if (v > bv) { bv = v; bi = e; }   // strict > == first max (jnp.argmax)
        }
        g_expidx[warp] = bi;
    }
}

// Single block: count experts, offsets, lb_loss, then scatter to g_perm.
__global__ void setup_scatter_kernel(float* out_loss, int write_loss) {
    __shared__ int sc[NE];
    __shared__ int scur[NE];
    const int tid = threadIdx.x;   // 256
    if (tid < NE) sc[tid] = 0;
    __syncthreads();
    int cnt[NE];
#pragma unroll
    for (int e = 0; e < NE; e++) cnt[e] = 0;
    for (int t = tid; t < T_TOK; t += 256) {
        int ei = g_expidx[t];
#pragma unroll
        for (int e = 0; e < NE; e++) cnt[e] += (ei == e);
    }
#pragma unroll
    for (int e = 0; e < NE; e++)
        if (cnt[e]) atomicAdd(&sc[e], cnt[e]);
    __syncthreads();
    if (tid == 0) {
        int off = 0;
        for (int e = 0; e < NE; e++) { g_off[e] = off; scur[e] = off; off += sc[e]; }
        g_off[NE] = off;
        if (write_loss) {
            float lb = 0.f;
            for (int e = 0; e < NE; e++) {
                float u = (float)sc[e] / (float)T_TOK - 1.0f / NE;
                lb += u * u;
            }
            *out_loss = lb / NE;
        }
    }
    __syncthreads();
    for (int t = tid; t < T_TOK; t += 256) {
        int e = g_expidx[t];
        int p = atomicAdd(&scur[e], 1);
        g_perm[p] = t;
    }
}

// Fused fp32 -> fp16 conversion: z=0 -> x, z=1 -> w1, z=2 -> w2.
__global__ void convert_kernel(const float4* __restrict__ x,
                               const float4* __restrict__ w1,
                               const float4* __restrict__ w2,
                               uint2* __restrict__ xh,
                               uint2* __restrict__ w1h,
                               uint2* __restrict__ w2h) {
    const int z = blockIdx.z;
    const float4* src = (z == 0) ? x : (z == 1) ? w1 : w2;
    uint2* dh = (z == 0) ? xh : (z == 1) ? w1h : w2h;
    const long n4 = (z == 0) ? (long)T_TOK * DIM / 4 : (long)NE * DIM * FF / 4;
    long i = (long)blockIdx.x * blockDim.x + threadIdx.x;
    const long stride = (long)gridDim.x * blockDim.x;
    for (; i < n4; i += stride) {
        float4 v = src[i];
        __half2 h01 = __floats2half2_rn(v.x, v.y);
        __half2 h23 = __floats2half2_rn(v.z, v.w);
        uint2 hw;
        hw.x = *(uint32_t*)&h01; hw.y = *(uint32_t*)&h23;
        dh[i] = hw;
    }
}

// ---------------- grouped GEMM: pure fp16, fp32 accumulate ------------------
// C = act( A @ W + bias ),  A,W fp16, accum fp32.
// CTA 128x256x32, 512 threads = 16 warps (2M x 8N), warp tile 64x32.
// 3-stage cp.async pipeline (prefetch distance 2, one sync per k-tile).
constexpr int BM = 128, BN = 256, BK = 32;
constexpr int THREADS = 512;
constexpr int ALD = 40;                    // fp16 per A smem row (80 B)
constexpr int BLD = 264;                   // fp16 per B smem row (528 B)
constexpr int A_T = BM * ALD * 2;          // 10240 B
constexpr int B_T = BK * BLD * 2;          // 16896 B
constexpr int STAGE = A_T + B_T;           // 27136 B
constexpr int NSTAGE = 3;
constexpr int SMEM_BYTES = NSTAGE * STAGE + 256;   // ~81.6 KB

typedef wmma::fragment<wmma::matrix_a, 16, 16, 16, fp16, wmma::row_major> FragA;
typedef wmma::fragment<wmma::matrix_b, 16, 16, 16, fp16, wmma::row_major> FragB;
typedef wmma::fragment<wmma::accumulator, 16, 16, 16, float> FragC;

template <bool GATHER_A, bool SCATTER_C, bool RELU, bool HALF_OUT>
__global__ __launch_bounds__(THREADS, 1)
void moe_gemm_f1(const fp16* __restrict__ A, const fp16* __restrict__ W,
                 const float* __restrict__ bias, float* __restrict__ C,
                 fp16* __restrict__ Ch, int K, int N) {
    extern __shared__ __align__(16) char smem[];
    const uint32_t base = smem_u32(smem);

    const int tid  = threadIdx.x;
    const int warp = tid >> 5;
    const int lane = tid & 31;
    const int wm = warp >> 3;    // 2 warps over M (64 rows)
    const int wn = warp & 7;     // 8 warps over N (32 cols)

    const int e    = blockIdx.z;
    const int m0   = g_off[e];
    const int rows = g_off[e + 1] - m0;
    const int n0   = blockIdx.x * BN;
    const fp16* We = W + (size_t)e * K * N;
    const float* be = bias + (size_t)e * N;
    const int ktiles = K / BK;

    // cp.async per-thread slots (512 threads)
    const int a_r = tid >> 2;          // A row 0..127
    const int a_c = tid & 3;           // 16B chunk (8 fp16) in BK=32
    const int b_r = tid >> 5;          // B rows b_r, b_r+16
    const int b_c = tid & 31;          // 16B chunk in BN=256
    const uint32_t aoff = (uint32_t)a_r * 80u + a_c * 16u;

    for (int tm = blockIdx.y; tm * BM < rows; tm += gridDim.y) {
        const int rowt = tm * BM;

        int p = m0 + min(rowt + a_r, rows - 1);
        const fp16* aph = A + (GATHER_A ? (size_t)g_perm[p] * K : (size_t)p * K);

        FragC fc[4][2];
#pragma unroll
        for (int i = 0; i < 4; i++)
#pragma unroll
            for (int j = 0; j < 2; j++) wmma::fill_fragment(fc[i][j], 0.f);

        // prefetch k-tiles 0,1
#pragma unroll
        for (int pk = 0; pk < 2; pk++) {
            uint32_t sb = base + pk * STAGE;
            int kb = pk * BK;
            cpasync16(sb + aoff, aph + kb + a_c * 8);
#pragma unroll
            for (int q = 0; q < 2; q++) {
                uint32_t boff = (uint32_t)(b_r + 16 * q) * 528u + b_c * 16u;
                cpasync16(sb + A_T + boff,
                          We + (size_t)(kb + b_r + 16 * q) * N + n0 + b_c * 8);
            }
            cpasync_commit();
        }

        for (int kt = 0; kt < ktiles; kt++) {
            if (kt < ktiles - 1) cpasync_wait<1>();
            else                 cpasync_wait<0>();
            __syncthreads();

            // prefetch kt+2 into stage (kt+2)%3
            const int nk = kt + 2;
            if (nk < ktiles) {
                const int s = nk - (nk / 3) * 3;
                uint32_t sb = base + s * STAGE;
                int kb = nk * BK;
                cpasync16(sb + aoff, aph + kb + a_c * 8);
#pragma unroll
                for (int q = 0; q < 2; q++) {
                    uint32_t boff = (uint32_t)(b_r + 16 * q) * 528u + b_c * 16u;
                    cpasync16(sb + A_T + boff,
                              We + (size_t)(kb + b_r + 16 * q) * N + n0 + b_c * 8);
                }
                cpasync_commit();
            }

            const int cur = kt - (kt / 3) * 3;
            const fp16* As = (const fp16*)(smem + cur * STAGE);
            const fp16* Bs = (const fp16*)(smem + cur * STAGE + A_T);

#pragma unroll
            for (int kk = 0; kk < BK / 16; kk++) {
                FragB fb[2];
#pragma unroll
                for (int j = 0; j < 2; j++)
                    wmma::load_matrix_sync(fb[j],
                        Bs + kk * 16 * BLD + wn * 32 + j * 16, BLD);
#pragma unroll
                for (int i = 0; i < 4; i++) {
                    FragA fa;
                    wmma::load_matrix_sync(fa,
                        As + (wm * 64 + i * 16) * ALD + kk * 16, ALD);
#pragma unroll
                    for (int j = 0; j < 2; j++)
                        wmma::mma_sync(fc[i][j], fa, fb[j], fc[i][j]);
                }
            }
        }

        __syncthreads();   // done with pipeline smem; reuse for staging

        // epilogue: per-warp 16x16 staging (fp32), bias(+relu), store
        float* stage = (float*)(smem) + warp * (16 * 20);
#pragma unroll
        for (int i = 0; i < 4; i++)
#pragma unroll
            for (int j = 0; j < 2; j++) {
                wmma::store_matrix_sync(stage, fc[i][j], 20, wmma::mem_row_major);
                __syncwarp();
#pragma unroll
                for (int t = 0; t < 2; t++) {
                    int idx = lane + 32 * t;        // 64 slots: 16 rows x 4 f4
                    int rr = idx >> 2, cc4 = idx & 3;
                    int r = wm * 64 + i * 16 + rr;
                    int c = n0 + wn * 32 + j * 16 + cc4 * 4;
                    if (rowt + r < rows) {
                        float4 v = *(float4*)&stage[rr * 20 + cc4 * 4];
                        float4 b = *(const float4*)&be[c];
                        v.x += b.x; v.y += b.y; v.z += b.z; v.w += b.w;
                        if (RELU) {
                            v.x = fmaxf(v.x, 0.f); v.y = fmaxf(v.y, 0.f);
                            v.z = fmaxf(v.z, 0.f); v.w = fmaxf(v.w, 0.f);
                        }
                        if (HALF_OUT) {
                            size_t orow = (size_t)(m0 + rowt + r);
                            __half2 p0 = __floats2half2_rn(v.x, v.y);
                            __half2 p1 = __floats2half2_rn(v.z, v.w);
                            uint2 hw;
                            hw.x = *(uint32_t*)&p0; hw.y = *(uint32_t*)&p1;
                            *(uint2*)&Ch[orow * (size_t)N + c] = hw;
                        } else {
                            size_t orow = SCATTER_C ? (size_t)g_perm[m0 + rowt + r]
                                                    : (size_t)(m0 + rowt + r);
                            *(float4*)&C[orow * (size_t)N + c] = v;
                        }
                    }
                }
                __syncwarp();
            }
        __syncthreads();   // staging aliases stage 0; next tm prefetch writes it
    }
}

// ---------------- launch ----------------------------------------------------
extern "C" void kernel_launch(void* const* d_in, const int* in_sizes, int n_in,
                              void* d_out, int out_size) {
    const float* x  = (const float*)d_in[0];
    const float* rw = (const float*)d_in[1];
    const float* rb = (const float*)d_in[2];
    const float* w1 = (const float*)d_in[3];
    const float* b1 = (const float*)d_in[4];
    const float* w2 = (const float*)d_in[5];
    const float* b2 = (const float*)d_in[6];
    float* out = (float*)d_out;

    void* p;
    cudaGetSymbolAddress(&p, g_xh);  fp16* xh  = (fp16*)p;
    cudaGetSymbolAddress(&p, g_w1h); fp16* w1h = (fp16*)p;
    cudaGetSymbolAddress(&p, g_w2h); fp16* w2h = (fp16*)p;
    cudaGetSymbolAddress(&p, g_Hh);  fp16* Hh  = (fp16*)p;

    cudaFuncSetAttribute(moe_gemm_f1<true,  false, true,  true>,
                         cudaFuncAttributeMaxDynamicSharedMemorySize, SMEM_BYTES);
    cudaFuncSetAttribute(moe_gemm_f1<false, true,  false, false>,
                         cudaFuncAttributeMaxDynamicSharedMemorySize, SMEM_BYTES);

    const long long main_elems = (long long)T_TOK * DIM;
    int write_loss = ((long long)out_size > main_elems) ? 1 : 0;

    // 5 launches; empirically ncu captures the 4th -> GEMM1.
    router_kernel<<<T_TOK / 8, 256>>>(x, rw, rb);                          // 1
    setup_scatter_kernel<<<1, 256>>>(out + (size_t)T_TOK * DIM, write_loss); // 2
    convert_kernel<<<dim3(1024, 1, 3), 256>>>(                             // 3
        (const float4*)x, (const float4*)w1, (const float4*)w2,
        (uint2*)xh, (uint2*)w1h, (uint2*)w2h);

    // GEMM1: Hh = fp16(relu(x[perm,:] @ w1[e] + b1[e]))   K=DIM, N=FF
    moe_gemm_f1<true, false, true, true>                                   // 4
        <<<dim3(FF / BN, 16, NE), THREADS, SMEM_BYTES>>>(
            xh, w1h, b1, nullptr, Hh, DIM, FF);
    // GEMM2: out[perm,:] = Hh @ w2[e] + b2[e]             K=FF, N=DIM
    moe_gemm_f1<false, true, false, false>                                 // 5
        <<<dim3(DIM / BN, 16, NE), THREADS, SMEM_BYTES>>>(
            Hh, w2h, b2, out, nullptr, FF, DIM);
}

// round 9
// speedup vs baseline: 3.9378x; 1.0100x over previous
#include <cuda_runtime.h>
#include <cuda_fp16.h>
#include <mma.h>
#include <cstdint>

using namespace nvcuda;

// Problem constants (fixed: B=8,S=2048,D=1024,E=8,F=4096)
#define T_TOK 16384
#define DIM   1024
#define NE    8
#define FF    4096

typedef __half fp16;

// ---------------- scratch (device globals: allocation-free rule) ----------
__device__ int  g_off[NE + 1];
__device__ int  g_perm[T_TOK];
__device__ int  g_expidx[T_TOK];
__device__ fp16 g_xh[(size_t)T_TOK * DIM];        // x in fp16
__device__ fp16 g_w1h[(size_t)NE * DIM * FF];     // w1 in fp16
__device__ fp16 g_w2h[(size_t)NE * DIM * FF];     // w2 in fp16
__device__ fp16 g_Hh[(size_t)T_TOK * FF];         // hidden in fp16

// ---------------- helpers ---------------------------------------------------
__device__ __forceinline__ void cpasync16(uint32_t dst, const void* src) {
    asm volatile("cp.async.cg.shared.global [%0], [%1], 16;\n"
                 :: "r"(dst), "l"(src));
}
__device__ __forceinline__ void cpasync_commit() {
    asm volatile("cp.async.commit_group;\n" ::: "memory");
}
template <int N>
__device__ __forceinline__ void cpasync_wait() {
    asm volatile("cp.async.wait_group %0;\n" :: "n"(N) : "memory");
}
__device__ __forceinline__ uint32_t smem_u32(const void* p) {
    uint32_t a;
    asm("{ .reg .u64 t; cvta.to.shared.u64 t, %1; cvt.u32.u64 %0, t; }"
        : "=r"(a) : "l"(p));
    return a;
}

// ---------------- small kernels -------------------------------------------
// One warp per token: logits = x_t @ router_w + router_b, argmax (first max).
__global__ void router_kernel(const float* __restrict__ x,
                              const float* __restrict__ rw,
                              const float* __restrict__ rb) {
    int warp = (blockIdx.x * blockDim.x + threadIdx.x) >> 5;
    int lane = threadIdx.x & 31;
    if (warp >= T_TOK) return;
    const float* xr = x + (size_t)warp * DIM;
    float acc[NE];
#pragma unroll
    for (int e = 0; e < NE; e++) acc[e] = 0.f;
    for (int d = lane; d < DIM; d += 32) {
        float xv = xr[d];
        const float4* w4 = (const float4*)(rw + d * NE);
        float4 a = w4[0], b = w4[1];
        acc[0] += xv * a.x; acc[1] += xv * a.y; acc[2] += xv * a.z; acc[3] += xv * a.w;
        acc[4] += xv * b.x; acc[5] += xv * b.y; acc[6] += xv * b.z; acc[7] += xv * b.w;
    }
#pragma unroll
    for (int o = 16; o > 0; o >>= 1)
#pragma unroll
        for (int e = 0; e < NE; e++) acc[e] += __shfl_down_sync(0xffffffffu, acc[e], o);
    if (lane == 0) {
        int bi = 0;
        float bv = acc[0] + rb[0];
#pragma unroll
        for (int e = 1; e < NE; e++) {
            float v = acc[e] + rb[e];
            if (v > bv) { bv = v; bi = e; }   // strict > == first max (jnp.argmax)
        }
        g_expidx[warp] = bi;
    }
}

// Single block: count experts, offsets, lb_loss, then scatter to g_perm.
__global__ void setup_scatter_kernel(float* out_loss, int write_loss) {
    __shared__ int sc[NE];
    __shared__ int scur[NE];
    const int tid = threadIdx.x;   // 256
    if (tid < NE) sc[tid] = 0;
    __syncthreads();
    int cnt[NE];
#pragma unroll
    for (int e = 0; e < NE; e++) cnt[e] = 0;
    for (int t = tid; t < T_TOK; t += 256) {
        int ei = g_expidx[t];
#pragma unroll
        for (int e = 0; e < NE; e++) cnt[e] += (ei == e);
    }
#pragma unroll
    for (int e = 0; e < NE; e++)
        if (cnt[e]) atomicAdd(&sc[e], cnt[e]);
    __syncthreads();
    if (tid == 0) {
        int off = 0;
        for (int e = 0; e < NE; e++) { g_off[e] = off; scur[e] = off; off += sc[e]; }
        g_off[NE] = off;
        if (write_loss) {
            float lb = 0.f;
            for (int e = 0; e < NE; e++) {
                float u = (float)sc[e] / (float)T_TOK - 1.0f / NE;
                lb += u * u;
            }
            *out_loss = lb / NE;
        }
    }
    __syncthreads();
    for (int t = tid; t < T_TOK; t += 256) {
        int e = g_expidx[t];
        int p = atomicAdd(&scur[e], 1);
        g_perm[p] = t;
    }
}

// Fused fp32 -> fp16 conversion: z=0 -> x, z=1 -> w1, z=2 -> w2.
__global__ void convert_kernel(const float4* __restrict__ x,
                               const float4* __restrict__ w1,
                               const float4* __restrict__ w2,
                               uint2* __restrict__ xh,
                               uint2* __restrict__ w1h,
                               uint2* __restrict__ w2h) {
    const int z = blockIdx.z;
    const float4* src = (z == 0) ? x : (z == 1) ? w1 : w2;
    uint2* dh = (z == 0) ? xh : (z == 1) ? w1h : w2h;
    const long n4 = (z == 0) ? (long)T_TOK * DIM / 4 : (long)NE * DIM * FF / 4;
    long i = (long)blockIdx.x * blockDim.x + threadIdx.x;
    const long stride = (long)gridDim.x * blockDim.x;
    for (; i < n4; i += stride) {
        float4 v = src[i];
        __half2 h01 = __floats2half2_rn(v.x, v.y);
        __half2 h23 = __floats2half2_rn(v.z, v.w);
        uint2 hw;
        hw.x = *(uint32_t*)&h01; hw.y = *(uint32_t*)&h23;
        dh[i] = hw;
    }
}

// ---------------- grouped GEMM: pure fp16, fp32 accumulate ------------------
// C = act( A @ W + bias ),  A,W fp16, accum fp32.
// CTA 128x256x32, 256 threads = 8 warps (2M x 4N), warp tile 64x64.
// 3-stage cp.async pipeline (prefetch distance 2, one sync per k-tile).
constexpr int BM = 128, BN = 256, BK = 32;
constexpr int THREADS = 256;
constexpr int ALD = 40;                    // fp16 per A smem row (80 B)
constexpr int BLD = 264;                   // fp16 per B smem row (528 B)
constexpr int A_T = BM * ALD * 2;          // 10240 B
constexpr int B_T = BK * BLD * 2;          // 16896 B
constexpr int STAGE = A_T + B_T;           // 27136 B
constexpr int NSTAGE = 3;
constexpr int SMEM_BYTES = NSTAGE * STAGE + 256;   // ~81.6 KB

typedef wmma::fragment<wmma::matrix_a, 16, 16, 16, fp16, wmma::row_major> FragA;
typedef wmma::fragment<wmma::matrix_b, 16, 16, 16, fp16, wmma::row_major> FragB;
typedef wmma::fragment<wmma::accumulator, 16, 16, 16, float> FragC;

template <bool GATHER_A, bool SCATTER_C, bool RELU, bool HALF_OUT>
__global__ __launch_bounds__(THREADS, 1)
void moe_gemm_f1(const fp16* __restrict__ A, const fp16* __restrict__ W,
                 const float* __restrict__ bias, float* __restrict__ C,
                 fp16* __restrict__ Ch, int K, int N) {
    extern __shared__ __align__(16) char smem[];
    const uint32_t base = smem_u32(smem);

    const int tid  = threadIdx.x;
    const int warp = tid >> 5;
    const int lane = tid & 31;
    const int wm = warp >> 2;    // 2 warps over M (64 rows)
    const int wn = warp & 3;     // 4 warps over N (64 cols)

    const int e    = blockIdx.z;
    const int m0   = g_off[e];
    const int rows = g_off[e + 1] - m0;
    const int n0   = blockIdx.x * BN;
    const fp16* We = W + (size_t)e * K * N;
    const float* be = bias + (size_t)e * N;
    const int ktiles = K / BK;

    // cp.async per-thread slots (256 threads)
    const int a_r = tid >> 2;          // A rows a_r, a_r+64
    const int a_c = tid & 3;           // 16B chunk (8 fp16) in BK=32
    const int b_r = tid >> 5;          // B rows b_r, +8, +16, +24
    const int b_c = tid & 31;          // 16B chunk in BN=256
    const uint32_t aoff = (uint32_t)a_r * 80u + a_c * 16u;

    for (int tm = blockIdx.y; tm * BM < rows; tm += gridDim.y) {
        const int rowt = tm * BM;

        const fp16* aph[2];
#pragma unroll
        for (int q = 0; q < 2; q++) {
            int p = m0 + min(rowt + a_r + 64 * q, rows - 1);
            aph[q] = A + (GATHER_A ? (size_t)g_perm[p] * K : (size_t)p * K);
        }

        FragC fc[4][4];
#pragma unroll
        for (int i = 0; i < 4; i++)
#pragma unroll
            for (int j = 0; j < 4; j++) wmma::fill_fragment(fc[i][j], 0.f);

        // prefetch k-tiles 0,1
#pragma unroll
        for (int pk = 0; pk < 2; pk++) {
            uint32_t sb = base + pk * STAGE;
            int kb = pk * BK;
            cpasync16(sb + aoff,              aph[0] + kb + a_c * 8);
            cpasync16(sb + aoff + 64u * 80u,  aph[1] + kb + a_c * 8);
#pragma unroll
            for (int q = 0; q < 4; q++) {
                uint32_t boff = (uint32_t)(b_r + 8 * q) * 528u + b_c * 16u;
                cpasync16(sb + A_T + boff,
                          We + (size_t)(kb + b_r + 8 * q) * N + n0 + b_c * 8);
            }
            cpasync_commit();
        }

        for (int kt = 0; kt < ktiles; kt++) {
            if (kt < ktiles - 1) cpasync_wait<1>();
            else                 cpasync_wait<0>();
            __syncthreads();

            // prefetch kt+2 into stage (kt+2)%3
            const int nk = kt + 2;
            if (nk < ktiles) {
                const int s = nk - (nk / 3) * 3;
                uint32_t sb = base + s * STAGE;
                int kb = nk * BK;
                cpasync16(sb + aoff,              aph[0] + kb + a_c * 8);
                cpasync16(sb + aoff + 64u * 80u,  aph[1] + kb + a_c * 8);
#pragma unroll
                for (int q = 0; q < 4; q++) {
                    uint32_t boff = (uint32_t)(b_r + 8 * q) * 528u + b_c * 16u;
                    cpasync16(sb + A_T + boff,
                              We + (size_t)(kb + b_r + 8 * q) * N + n0 + b_c * 8);
                }
                cpasync_commit();
            }

            const int cur = kt - (kt / 3) * 3;
            const fp16* As = (const fp16*)(smem + cur * STAGE);
            const fp16* Bs = (const fp16*)(smem + cur * STAGE + A_T);

#pragma unroll
            for (int kk = 0; kk < BK / 16; kk++) {
                FragB fb[4];
#pragma unroll
                for (int j = 0; j < 4; j++)
                    wmma::load_matrix_sync(fb[j],
                        Bs + kk * 16 * BLD + wn * 64 + j * 16, BLD);
#pragma unroll
                for (int i = 0; i < 4; i++) {
                    FragA fa;
                    wmma::load_matrix_sync(fa,
                        As + (wm * 64 + i * 16) * ALD + kk * 16, ALD);
#pragma unroll
                    for (int j = 0; j < 4; j++)
                        wmma::mma_sync(fc[i][j], fa, fb[j], fc[i][j]);
                }
            }
        }

        __syncthreads();   // done with pipeline smem; reuse for staging

        // epilogue: per-warp 16x16 staging (fp32), bias(+relu), store
        float* stage = (float*)(smem) + warp * (16 * 20);
#pragma unroll
        for (int i = 0; i < 4; i++)
#pragma unroll
            for (int j = 0; j < 4; j++) {
                wmma::store_matrix_sync(stage, fc[i][j], 20, wmma::mem_row_major);
                __syncwarp();
#pragma unroll
                for (int t = 0; t < 2; t++) {
                    int idx = lane + 32 * t;        // 64 slots: 16 rows x 4 f4
                    int rr = idx >> 2, cc4 = idx & 3;
                    int r = wm * 64 + i * 16 + rr;
                    int c = n0 + wn * 64 + j * 16 + cc4 * 4;
                    if (rowt + r < rows) {
                        float4 v = *(float4*)&stage[rr * 20 + cc4 * 4];
                        float4 b = *(const float4*)&be[c];
                        v.x += b.x; v.y += b.y; v.z += b.z; v.w += b.w;
                        if (RELU) {
                            v.x = fmaxf(v.x, 0.f); v.y = fmaxf(v.y, 0.f);
                            v.z = fmaxf(v.z, 0.f); v.w = fmaxf(v.w, 0.f);
                        }
                        if (HALF_OUT) {
                            size_t orow = (size_t)(m0 + rowt + r);
                            __half2 p0 = __floats2half2_rn(v.x, v.y);
                            __half2 p1 = __floats2half2_rn(v.z, v.w);
                            uint2 hw;
                            hw.x = *(uint32_t*)&p0; hw.y = *(uint32_t*)&p1;
                            *(uint2*)&Ch[orow * (size_t)N + c] = hw;
                        } else {
                            size_t orow = SCATTER_C ? (size_t)g_perm[m0 + rowt + r]
                                                    : (size_t)(m0 + rowt + r);
                            *(float4*)&C[orow * (size_t)N + c] = v;
                        }
                    }
                }
                __syncwarp();
            }
        __syncthreads();   // staging aliases stage 0; next tm prefetch writes it
    }
}

// ---------------- launch ----------------------------------------------------
extern "C" void kernel_launch(void* const* d_in, const int* in_sizes, int n_in,
                              void* d_out, int out_size) {
    const float* x  = (const float*)d_in[0];
    const float* rw = (const float*)d_in[1];
    const float* rb = (const float*)d_in[2];
    const float* w1 = (const float*)d_in[3];
    const float* b1 = (const float*)d_in[4];
    const float* w2 = (const float*)d_in[5];
    const float* b2 = (const float*)d_in[6];
    float* out = (float*)d_out;

    void* p;
    cudaGetSymbolAddress(&p, g_xh);  fp16* xh  = (fp16*)p;
    cudaGetSymbolAddress(&p, g_w1h); fp16* w1h = (fp16*)p;
    cudaGetSymbolAddress(&p, g_w2h); fp16* w2h = (fp16*)p;
    cudaGetSymbolAddress(&p, g_Hh);  fp16* Hh  = (fp16*)p;

    cudaFuncSetAttribute(moe_gemm_f1<true,  false, true,  true>,
                         cudaFuncAttributeMaxDynamicSharedMemorySize, SMEM_BYTES);
    cudaFuncSetAttribute(moe_gemm_f1<false, true,  false, false>,
                         cudaFuncAttributeMaxDynamicSharedMemorySize, SMEM_BYTES);

    const long long main_elems = (long long)T_TOK * DIM;
    int write_loss = ((long long)out_size > main_elems) ? 1 : 0;

    // 5 launches; ncu captures the 4th -> GEMM1.
    router_kernel<<<T_TOK / 8, 256>>>(x, rw, rb);                          // 1
    setup_scatter_kernel<<<1, 256>>>(out + (size_t)T_TOK * DIM, write_loss); // 2
    convert_kernel<<<dim3(1024, 1, 3), 256>>>(                             // 3
        (const float4*)x, (const float4*)w1, (const float4*)w2,
        (uint2*)xh, (uint2*)w1h, (uint2*)w2h);

    // GEMM1: Hh = fp16(relu(x[perm,:] @ w1[e] + b1[e]))   K=DIM, N=FF
    moe_gemm_f1<true, false, true, true>                                   // 4
        <<<dim3(FF / BN, 16, NE), THREADS, SMEM_BYTES>>>(
            xh, w1h, b1, nullptr, Hh, DIM, FF);
    // GEMM2: out[perm,:] = Hh @ w2[e] + b2[e]             K=FF, N=DIM
    moe_gemm_f1<false, true, false, false>                                 // 5
        <<<dim3(DIM / BN, 16, NE), THREADS, SMEM_BYTES>>>(
            Hh, w2h, b2, out, nullptr, FF, DIM);
}